// round 9
// baseline (speedup 1.0000x reference)
#include <cuda_runtime.h>
#include <cuda_bf16.h>
#include <cstdint>

// ---------------------------------------------------------------------------
// ConvTemporalGraphical — mma.sync bf16-split with register software pipeline,
// LDS.128 gconv, fused expert mix.
// K1: partials = x[32,204800] @ W0[204800,256] (3-term bf16 hi/lo mma.sync,
//     next-kstep B/x prefetched in registers to hide DRAM latency)
// K2: reduce 296 partials + b0 + ELU -> h0
// K3: gating fused: h1=ELU(h0@W1+b1); softmax(h1@W2+b2) -> w[32,4]
// K4: gconv: in-block expert mix, AS rows padded to 32 for LDS.128.
// ---------------------------------------------------------------------------

#define K_DIM 204800
#define M_DIM 32
#define N_DIM 256
#define SPLIT 296              // = 2 * 148 SMs -> balanced single wave
#define KSTEPS_TOTAL 12800     // K / 16

__device__ float g_partial[SPLIT * M_DIM * N_DIM];   // 9.7 MB
__device__ float g_h0[M_DIM * N_DIM];
__device__ float g_w[M_DIM * 4];

typedef unsigned long long u64;

__device__ __forceinline__ float elu(float v) { return v > 0.0f ? v : expm1f(v); }

__device__ __forceinline__ u64 pack2(float lo, float hi) {
    u64 r; asm("mov.b64 %0, {%1, %2};" : "=l"(r) : "f"(lo), "f"(hi)); return r;
}
__device__ __forceinline__ void unpack2(u64 v, float& lo, float& hi) {
    asm("mov.b64 {%0, %1}, %2;" : "=f"(lo), "=f"(hi) : "l"(v));
}
__device__ __forceinline__ void ffma2(u64& d, u64 a, u64 b) {
    asm("fma.rn.f32x2 %0, %1, %2, %0;" : "+l"(d) : "l"(a), "l"(b));
}

// split a float2 into bf16x2 hi and bf16x2 lo (residual)
__device__ __forceinline__ void split2(float a, float b, uint32_t& hi, uint32_t& lo) {
    __nv_bfloat162 h = __floats2bfloat162_rn(a, b);
    hi = *reinterpret_cast<uint32_t*>(&h);
    const float ra = a - __bfloat162float(h.x);
    const float rb = b - __bfloat162float(h.y);
    __nv_bfloat162 l = __floats2bfloat162_rn(ra, rb);
    lo = *reinterpret_cast<uint32_t*>(&l);
}

__device__ __forceinline__ void mma_bf16(float* d, const uint32_t* a,
                                         uint32_t b0, uint32_t b1) {
    asm volatile(
        "mma.sync.aligned.m16n8k16.row.col.f32.bf16.bf16.f32 "
        "{%0,%1,%2,%3}, {%4,%5,%6,%7}, {%8,%9}, {%0,%1,%2,%3};"
        : "+f"(d[0]), "+f"(d[1]), "+f"(d[2]), "+f"(d[3])
        : "r"(a[0]), "r"(a[1]), "r"(a[2]), "r"(a[3]), "r"(b0), "r"(b1));
}

// ---------------------------------------------------------------------------
// K1: block = variable K-chunk (43-44 k16-steps over 296 blocks).
// 8 warps; warp w owns n-range [w*32, w*32+32).
// Software pipeline: while converting+MMAing kstep ks, the 16 B floats and
// 8 x float2s of kstep ks+1 are already in flight (prefetch registers).
// ---------------------------------------------------------------------------
__global__ __launch_bounds__(256, 2)
void gemm0_mma(const float* __restrict__ x, const float* __restrict__ W0) {
    const int tid  = threadIdx.x;
    const int w    = tid >> 5;
    const int lane = tid & 31;
    const int g    = lane >> 2;    // 0..7
    const int tg   = lane & 3;     // 0..3
    const int nbase = w * 32;

    const int ks_beg = (int)(((long)blockIdx.x       * KSTEPS_TOTAL) / SPLIT);
    const int ks_end = (int)(((long)(blockIdx.x + 1) * KSTEPS_TOTAL) / SPLIT);

    float d[2][4][4];
#pragma unroll
    for (int mt = 0; mt < 2; mt++)
#pragma unroll
        for (int j = 0; j < 4; j++)
#pragma unroll
            for (int r = 0; r < 4; r++) d[mt][j][r] = 0.0f;

    float2 xp[2][4];     // prefetched x pairs
    float  bp[4][4];     // prefetched B scalars

    // prologue: load kstep ks_beg
    {
        const int kk = ks_beg * 16;
#pragma unroll
        for (int mt = 0; mt < 2; mt++) {
            const int r0 = mt * 16 + g;
            xp[mt][0] = *(const float2*)(x + r0 * K_DIM + kk + 2 * tg);
            xp[mt][1] = *(const float2*)(x + (r0 + 8) * K_DIM + kk + 2 * tg);
            xp[mt][2] = *(const float2*)(x + r0 * K_DIM + kk + 2 * tg + 8);
            xp[mt][3] = *(const float2*)(x + (r0 + 8) * K_DIM + kk + 2 * tg + 8);
        }
#pragma unroll
        for (int j = 0; j < 4; j++) {
            const float* q = W0 + (kk + 2 * tg) * N_DIM + nbase + j * 8 + g;
            bp[j][0] = q[0];
            bp[j][1] = q[N_DIM];
            bp[j][2] = q[8 * N_DIM];
            bp[j][3] = q[9 * N_DIM];
        }
    }

    for (int ks = ks_beg; ks < ks_end; ks++) {
        // ---- convert current A + B fragments from prefetch regs ----
        uint32_t ah[2][4], al[2][4];
#pragma unroll
        for (int mt = 0; mt < 2; mt++)
#pragma unroll
            for (int i = 0; i < 4; i++)
                split2(xp[mt][i].x, xp[mt][i].y, ah[mt][i], al[mt][i]);

        uint32_t bh[4][2], bl[4][2];
#pragma unroll
        for (int j = 0; j < 4; j++) {
            split2(bp[j][0], bp[j][1], bh[j][0], bl[j][0]);
            split2(bp[j][2], bp[j][3], bh[j][1], bl[j][1]);
        }

        // ---- issue next kstep's loads (latency hidden behind MMAs) ----
        const int kn = (ks + 1 < ks_end) ? (ks + 1) * 16 : ks * 16;
#pragma unroll
        for (int mt = 0; mt < 2; mt++) {
            const int r0 = mt * 16 + g;
            xp[mt][0] = *(const float2*)(x + r0 * K_DIM + kn + 2 * tg);
            xp[mt][1] = *(const float2*)(x + (r0 + 8) * K_DIM + kn + 2 * tg);
            xp[mt][2] = *(const float2*)(x + r0 * K_DIM + kn + 2 * tg + 8);
            xp[mt][3] = *(const float2*)(x + (r0 + 8) * K_DIM + kn + 2 * tg + 8);
        }
#pragma unroll
        for (int j = 0; j < 4; j++) {
            const float* q = W0 + (kn + 2 * tg) * N_DIM + nbase + j * 8 + g;
            bp[j][0] = q[0];
            bp[j][1] = q[N_DIM];
            bp[j][2] = q[8 * N_DIM];
            bp[j][3] = q[9 * N_DIM];
        }

        // ---- 24 MMAs ----
#pragma unroll
        for (int j = 0; j < 4; j++)
#pragma unroll
            for (int mt = 0; mt < 2; mt++) {
                mma_bf16(d[mt][j], ah[mt], bh[j][0], bh[j][1]);
                mma_bf16(d[mt][j], ah[mt], bl[j][0], bl[j][1]);
                mma_bf16(d[mt][j], al[mt], bh[j][0], bh[j][1]);
            }
    }

    float* po = g_partial + blockIdx.x * (M_DIM * N_DIM);
#pragma unroll
    for (int mt = 0; mt < 2; mt++) {
#pragma unroll
        for (int j = 0; j < 4; j++) {
            const int m0 = mt * 16 + g;
            const int n0 = nbase + j * 8 + 2 * tg;
            *(float2*)(po + m0 * N_DIM + n0)       = make_float2(d[mt][j][0], d[mt][j][1]);
            *(float2*)(po + (m0 + 8) * N_DIM + n0) = make_float2(d[mt][j][2], d[mt][j][3]);
        }
    }
}

// ---------------------------------------------------------------------------
// K2: reduce 296 partials (fixed order -> deterministic) + b0 + ELU.
// ---------------------------------------------------------------------------
__global__ __launch_bounds__(256)
void reduce_kernel(const float* __restrict__ b0) {
    __shared__ float red[8][32];
    const int m  = blockIdx.x >> 3;
    const int nc = (blockIdx.x & 7) * 32;
    const int nl = threadIdx.x & 31;
    const int sl = threadIdx.x >> 5;
    const int n  = nc + nl;

    float s = 0.0f;
    const float* p = g_partial + (sl * 37) * (M_DIM * N_DIM) + m * N_DIM + n;
#pragma unroll
    for (int i = 0; i < 37; i++) s += p[i * (M_DIM * N_DIM)];
    red[sl][nl] = s;
    __syncthreads();
    if (sl == 0) {
        float a = b0[n];
#pragma unroll
        for (int j = 0; j < 8; j++) a += red[j][nl];
        g_h0[m * N_DIM + n] = elu(a);
    }
}

// ---------------------------------------------------------------------------
// K3: fused gating; W1 loop with 4 independent accumulator chains.
// ---------------------------------------------------------------------------
__global__ __launch_bounds__(256)
void gating_kernel(const float* __restrict__ W1, const float* __restrict__ b1,
                   const float* __restrict__ W2, const float* __restrict__ b2) {
    __shared__ float hs[256];
    __shared__ float h1s[256];
    __shared__ float lg[4];
    const int m = blockIdx.x;
    const int n = threadIdx.x;

    hs[n] = g_h0[m * N_DIM + n];
    __syncthreads();

    float a0 = 0.0f, a1 = 0.0f, a2 = 0.0f, a3 = 0.0f;
#pragma unroll 8
    for (int k = 0; k < 64; k++) {
        a0 += hs[k]       * W1[k * 256 + n];
        a1 += hs[k + 64]  * W1[(k + 64) * 256 + n];
        a2 += hs[k + 128] * W1[(k + 128) * 256 + n];
        a3 += hs[k + 192] * W1[(k + 192) * 256 + n];
    }
    h1s[n] = elu(b1[n] + (a0 + a1) + (a2 + a3));
    __syncthreads();

    const int w = n >> 5, lane = n & 31;
    if (w < 4) {
        float s = 0.0f;
#pragma unroll
        for (int k = lane; k < 256; k += 32) s += h1s[k] * W2[k * 4 + w];
#pragma unroll
        for (int o = 16; o; o >>= 1) s += __shfl_xor_sync(0xffffffffu, s, o);
        if (lane == 0) lg[w] = s + b2[w];
    }
    __syncthreads();

    if (n < 4) {
        const float l0 = lg[0], l1 = lg[1], l2 = lg[2], l3 = lg[3];
        const float mx = fmaxf(fmaxf(l0, l1), fmaxf(l2, l3));
        const float e0 = expf(l0 - mx), e1 = expf(l1 - mx);
        const float e2 = expf(l2 - mx), e3 = expf(l3 - mx);
        const float inv = 1.0f / (e0 + e1 + e2 + e3);
        const float ev = (n == 0) ? e0 : (n == 1) ? e1 : (n == 2) ? e2 : e3;
        g_w[m * 4 + n] = ev * inv;
    }
}

// ---------------------------------------------------------------------------
// K4: block = (4 t's, n); 256 thr = 4 grp x 64 c.
// AS rows padded to 32 floats (128B) -> inner loop reads 6 LDS.128 + 1 LDS.32
// per v (was 13 LDS). AS reads broadcast; x from regs; staged coalesced I/O.
// ---------------------------------------------------------------------------
__global__ __launch_bounds__(256, 4)
void gconv_kernel(const float* __restrict__ x, const float* __restrict__ A,
                  float* __restrict__ out) {
    __shared__ __align__(16) float ASs[4][25 * 32];   // 12.8 KB
    __shared__ float buf[64 * 101];                   // 25.9 KB (xs then os)
    const int tid = threadIdx.x;
    const int n   = blockIdx.y;
    const int t0  = blockIdx.x * 4;

    const float w0 = g_w[n * 4 + 0];
    const float w1 = g_w[n * 4 + 1];
    const float w2 = g_w[n * 4 + 2];
    const float w3 = g_w[n * 4 + 3];

    // Phase 0: mixed adjacency (A[e,t,v,w] at (e*128 + t)*625)
    for (int idx = tid; idx < 2500; idx += 256) {
        const int grp = idx / 625;
        const int j   = idx - grp * 625;
        const int v   = j / 25;
        const int ww  = j - v * 25;
        const float* At = A + (t0 + grp) * 625 + j;
        ASs[grp][v * 32 + ww] = w0 * At[0]
                              + w1 * At[1 * 128 * 625]
                              + w2 * At[2 * 128 * 625]
                              + w3 * At[3 * 128 * 625];
    }

    // Phase 1: xs stage (coalesced 100-float runs per c)
    const float* xb = x + n * K_DIM + t0 * 25;
#pragma unroll
    for (int u = 0; u < 25; u++) {
        const int idx = u * 256 + tid;                 // 0..6399
        const int c = idx / 100;
        const int j = idx - c * 100;                   // grp*25 + v (contiguous)
        const int grp = j / 25;
        const int v   = j - grp * 25;
        buf[grp * 1600 + c * 25 + v] = xb[c * 3200 + j];
    }
    __syncthreads();

    const int grp = tid >> 6;
    const int c   = tid & 63;

    float rx[25];
    {
        const float* xr = &buf[grp * 1600 + c * 25];
#pragma unroll
        for (int v = 0; v < 25; v++) rx[v] = xr[v];
    }

    const float* Ab = &ASs[grp][0];
    u64 acc2[12];
#pragma unroll
    for (int p = 0; p < 12; p++) acc2[p] = 0ull;
    float acc24 = 0.0f;

#pragma unroll
    for (int v = 0; v < 25; v++) {
        const float gv = rx[v];
        const u64 gr = pack2(gv, gv);
        const float* row = Ab + v * 32;
#pragma unroll
        for (int q = 0; q < 6; q++) {
            const ulonglong2 pr = *(const ulonglong2*)(row + 4 * q);
            ffma2(acc2[2 * q],     gr, pr.x);
            ffma2(acc2[2 * q + 1], gr, pr.y);
        }
        acc24 += gv * row[24];
    }

    __syncthreads();   // done reading xs; reuse buf as os

    {
        float* os = &buf[c * 101 + grp * 25];
#pragma unroll
        for (int p = 0; p < 12; p++) {
            float lo, hi;
            unpack2(acc2[p], lo, hi);
            os[2 * p] = lo; os[2 * p + 1] = hi;
        }
        os[24] = acc24;
    }
    __syncthreads();

    // Phase 3: coalesced output
    float* ob = out + n * K_DIM + t0 * 25;
#pragma unroll
    for (int u = 0; u < 25; u++) {
        const int idx = u * 256 + tid;
        const int c2 = idx / 100;
        const int j  = idx - c2 * 100;
        ob[c2 * 3200 + j] = buf[c2 * 101 + j];
    }
}

// ---------------------------------------------------------------------------
extern "C" void kernel_launch(void* const* d_in, const int* in_sizes, int n_in,
                              void* d_out, int out_size) {
    const float* x  = (const float*)d_in[0];
    const float* W0 = (const float*)d_in[1];
    const float* b0 = (const float*)d_in[2];
    const float* W1 = (const float*)d_in[3];
    const float* b1 = (const float*)d_in[4];
    const float* W2 = (const float*)d_in[5];
    const float* b2 = (const float*)d_in[6];
    const float* A  = (const float*)d_in[7];
    float* out = (float*)d_out;

    gemm0_mma<<<SPLIT, 256>>>(x, W0);
    reduce_kernel<<<256, 256>>>(b0);
    gating_kernel<<<M_DIM, 256>>>(W1, b1, W2, b2);
    gconv_kernel<<<dim3(32, 32), 256>>>(x, A, out);
}

// round 10
// speedup vs baseline: 1.4695x; 1.4695x over previous
#include <cuda_runtime.h>
#include <cuda_bf16.h>
#include <cstdint>

// ---------------------------------------------------------------------------
// ConvTemporalGraphical — smem-staged bf16-split mma.sync GEMM + R7 gconv.
// K1: partials = x[32,204800] @ W0[204800,256]; W0/x tiles staged in smem as
//     bf16 hi/lo pair-rows (coalesced LDG.128, conflict-free LDS.32 frags).
// K2: reduce 296 partials + b0 + ELU -> h0
// K3: gating fused: h1=ELU(h0@W1+b1); softmax(h1@W2+b2) -> w[32,4]
// K4: gconv, in-block expert mix (R7 version: pad-26 rows, LDS.64 pairs).
// ---------------------------------------------------------------------------

#define K_DIM 204800
#define M_DIM 32
#define N_DIM 256
#define SPLIT 296              // = 2 * 148 SMs
#define TILES_TOTAL 6400       // K / 32

__device__ float g_partial[SPLIT * M_DIM * N_DIM];   // 9.7 MB
__device__ float g_h0[M_DIM * N_DIM];
__device__ float g_w[M_DIM * 4];

typedef unsigned long long u64;

__device__ __forceinline__ float elu(float v) { return v > 0.0f ? v : expm1f(v); }

__device__ __forceinline__ u64 pack2(float lo, float hi) {
    u64 r; asm("mov.b64 %0, {%1, %2};" : "=l"(r) : "f"(lo), "f"(hi)); return r;
}
__device__ __forceinline__ void unpack2(u64 v, float& lo, float& hi) {
    asm("mov.b64 {%0, %1}, %2;" : "=f"(lo), "=f"(hi) : "l"(v));
}
__device__ __forceinline__ void ffma2(u64& d, u64 a, u64 b) {
    asm("fma.rn.f32x2 %0, %1, %2, %0;" : "+l"(d) : "l"(a), "l"(b));
}

// split (a,b) into bf16x2 hi and bf16x2 lo (residual); .x=a(lo half), .y=b
__device__ __forceinline__ void split2(float a, float b, uint32_t& hi, uint32_t& lo) {
    __nv_bfloat162 h = __floats2bfloat162_rn(a, b);
    hi = *reinterpret_cast<uint32_t*>(&h);
    const float ra = a - __bfloat162float(h.x);
    const float rb = b - __bfloat162float(h.y);
    __nv_bfloat162 l = __floats2bfloat162_rn(ra, rb);
    lo = *reinterpret_cast<uint32_t*>(&l);
}

__device__ __forceinline__ void mma_bf16(float* d, const uint32_t* a,
                                         uint32_t b0, uint32_t b1) {
    asm volatile(
        "mma.sync.aligned.m16n8k16.row.col.f32.bf16.bf16.f32 "
        "{%0,%1,%2,%3}, {%4,%5,%6,%7}, {%8,%9}, {%0,%1,%2,%3};"
        : "+f"(d[0]), "+f"(d[1]), "+f"(d[2]), "+f"(d[3])
        : "r"(a[0]), "r"(a[1]), "r"(a[2]), "r"(a[3]), "r"(b0), "r"(b1));
}

// smem word strides: B rows pad 264 (264%32==8 -> banks 8*tg+g distinct),
// A rows pad 40 (40%32==8, same property).
#define BPAD 264
#define APAD 40
// dynamic smem layout (uint32 words)
#define OFF_BH 0
#define OFF_BL (16 * BPAD)
#define OFF_AH (32 * BPAD)
#define OFF_AL (32 * BPAD + 16 * APAD)
#define SMEM_WORDS (32 * BPAD + 32 * APAD)

// ---------------------------------------------------------------------------
// K1: block stages 32-k tiles (16 k-pairs) of W0 (32x256) and x (32x32) into
// smem as bf16 hi/lo pair-rows [kp][...], then 2 ksteps x 24 MMAs.
// Fragment reads are conflict-free LDS.32; W0 loads perfectly coalesced.
// ---------------------------------------------------------------------------
__global__ __launch_bounds__(256, 2)
void gemm0_mma(const float* __restrict__ x, const float* __restrict__ W0) {
    extern __shared__ uint32_t sm[];
    uint32_t* Bh  = sm + OFF_BH;
    uint32_t* Bl  = sm + OFF_BL;
    uint32_t* Ahs = sm + OFF_AH;
    uint32_t* Als = sm + OFF_AL;

    const int tid  = threadIdx.x;
    const int w    = tid >> 5;
    const int lane = tid & 31;
    const int g    = lane >> 2;    // 0..7
    const int tg   = lane & 3;     // 0..3
    const int nbase = w * 32;

    const int tl_beg = (int)(((long)blockIdx.x       * TILES_TOTAL) / SPLIT);
    const int tl_end = (int)(((long)(blockIdx.x + 1) * TILES_TOTAL) / SPLIT);

    float d[2][4][4];
#pragma unroll
    for (int mt = 0; mt < 2; mt++)
#pragma unroll
        for (int j = 0; j < 4; j++)
#pragma unroll
            for (int r = 0; r < 4; r++) d[mt][j][r] = 0.0f;

    for (int tl = tl_beg; tl < tl_end; tl++) {
        const int kb = tl * 32;
        __syncthreads();   // previous tile's reads complete

        // ---- stage B: 1024 tasks (kp, n-quad), coalesced LDG.128 ----
#pragma unroll
        for (int it = 0; it < 4; it++) {
            const int task = it * 256 + tid;
            const int kp = task >> 6;
            const int qn = (task & 63) * 4;
            const float4 r0 = *(const float4*)(W0 + (long)(kb + 2 * kp)     * N_DIM + qn);
            const float4 r1 = *(const float4*)(W0 + (long)(kb + 2 * kp + 1) * N_DIM + qn);
            uint32_t h[4], l[4];
            split2(r0.x, r1.x, h[0], l[0]);
            split2(r0.y, r1.y, h[1], l[1]);
            split2(r0.z, r1.z, h[2], l[2]);
            split2(r0.w, r1.w, h[3], l[3]);
            *(uint4*)&Bh[kp * BPAD + qn] = make_uint4(h[0], h[1], h[2], h[3]);
            *(uint4*)&Bl[kp * BPAD + qn] = make_uint4(l[0], l[1], l[2], l[3]);
        }
        // ---- stage A: 512 tasks (m, kp), coalesced float2 ----
#pragma unroll
        for (int it = 0; it < 2; it++) {
            const int task = it * 256 + tid;
            const int m  = task >> 4;
            const int kp = task & 15;
            const float2 p = *(const float2*)(x + (long)m * K_DIM + kb + 2 * kp);
            uint32_t h, l;
            split2(p.x, p.y, h, l);
            Ahs[kp * APAD + m] = h;
            Als[kp * APAD + m] = l;
        }
        __syncthreads();

        // ---- compute: 2 ksteps of 16 ----
#pragma unroll
        for (int s = 0; s < 2; s++) {
            const int kp0 = s * 8 + tg;
            const int kp1 = kp0 + 4;

            uint32_t ah[2][4], al[2][4];
#pragma unroll
            for (int mt = 0; mt < 2; mt++) {
                const int m0 = mt * 16 + g;
                ah[mt][0] = Ahs[kp0 * APAD + m0];
                ah[mt][1] = Ahs[kp0 * APAD + m0 + 8];
                ah[mt][2] = Ahs[kp1 * APAD + m0];
                ah[mt][3] = Ahs[kp1 * APAD + m0 + 8];
                al[mt][0] = Als[kp0 * APAD + m0];
                al[mt][1] = Als[kp0 * APAD + m0 + 8];
                al[mt][2] = Als[kp1 * APAD + m0];
                al[mt][3] = Als[kp1 * APAD + m0 + 8];
            }
#pragma unroll
            for (int j = 0; j < 4; j++) {
                const int n = nbase + j * 8 + g;
                const uint32_t bh0 = Bh[kp0 * BPAD + n];
                const uint32_t bh1 = Bh[kp1 * BPAD + n];
                const uint32_t bl0 = Bl[kp0 * BPAD + n];
                const uint32_t bl1 = Bl[kp1 * BPAD + n];
#pragma unroll
                for (int mt = 0; mt < 2; mt++) {
                    mma_bf16(d[mt][j], ah[mt], bh0, bh1);
                    mma_bf16(d[mt][j], ah[mt], bl0, bl1);
                    mma_bf16(d[mt][j], al[mt], bh0, bh1);
                }
            }
        }
    }

    float* po = g_partial + blockIdx.x * (M_DIM * N_DIM);
#pragma unroll
    for (int mt = 0; mt < 2; mt++) {
#pragma unroll
        for (int j = 0; j < 4; j++) {
            const int m0 = mt * 16 + g;
            const int n0 = nbase + j * 8 + 2 * tg;
            *(float2*)(po + m0 * N_DIM + n0)       = make_float2(d[mt][j][0], d[mt][j][1]);
            *(float2*)(po + (m0 + 8) * N_DIM + n0) = make_float2(d[mt][j][2], d[mt][j][3]);
        }
    }
}

// ---------------------------------------------------------------------------
// K2: reduce 296 partials (fixed order -> deterministic) + b0 + ELU.
// ---------------------------------------------------------------------------
__global__ __launch_bounds__(256)
void reduce_kernel(const float* __restrict__ b0) {
    __shared__ float red[8][32];
    const int m  = blockIdx.x >> 3;
    const int nc = (blockIdx.x & 7) * 32;
    const int nl = threadIdx.x & 31;
    const int sl = threadIdx.x >> 5;
    const int n  = nc + nl;

    float s = 0.0f;
    const float* p = g_partial + (sl * 37) * (M_DIM * N_DIM) + m * N_DIM + n;
#pragma unroll
    for (int i = 0; i < 37; i++) s += p[i * (M_DIM * N_DIM)];
    red[sl][nl] = s;
    __syncthreads();
    if (sl == 0) {
        float a = b0[n];
#pragma unroll
        for (int j = 0; j < 8; j++) a += red[j][nl];
        g_h0[m * N_DIM + n] = elu(a);
    }
}

// ---------------------------------------------------------------------------
// K3: fused gating; W1 loop with 4 independent accumulator chains.
// ---------------------------------------------------------------------------
__global__ __launch_bounds__(256)
void gating_kernel(const float* __restrict__ W1, const float* __restrict__ b1,
                   const float* __restrict__ W2, const float* __restrict__ b2) {
    __shared__ float hs[256];
    __shared__ float h1s[256];
    __shared__ float lg[4];
    const int m = blockIdx.x;
    const int n = threadIdx.x;

    hs[n] = g_h0[m * N_DIM + n];
    __syncthreads();

    float a0 = 0.0f, a1 = 0.0f, a2 = 0.0f, a3 = 0.0f;
#pragma unroll 8
    for (int k = 0; k < 64; k++) {
        a0 += hs[k]       * W1[k * 256 + n];
        a1 += hs[k + 64]  * W1[(k + 64) * 256 + n];
        a2 += hs[k + 128] * W1[(k + 128) * 256 + n];
        a3 += hs[k + 192] * W1[(k + 192) * 256 + n];
    }
    h1s[n] = elu(b1[n] + (a0 + a1) + (a2 + a3));
    __syncthreads();

    const int w = n >> 5, lane = n & 31;
    if (w < 4) {
        float s = 0.0f;
#pragma unroll
        for (int k = lane; k < 256; k += 32) s += h1s[k] * W2[k * 4 + w];
#pragma unroll
        for (int o = 16; o; o >>= 1) s += __shfl_xor_sync(0xffffffffu, s, o);
        if (lane == 0) lg[w] = s + b2[w];
    }
    __syncthreads();

    if (n < 4) {
        const float l0 = lg[0], l1 = lg[1], l2 = lg[2], l3 = lg[3];
        const float mx = fmaxf(fmaxf(l0, l1), fmaxf(l2, l3));
        const float e0 = expf(l0 - mx), e1 = expf(l1 - mx);
        const float e2 = expf(l2 - mx), e3 = expf(l3 - mx);
        const float inv = 1.0f / (e0 + e1 + e2 + e3);
        const float ev = (n == 0) ? e0 : (n == 1) ? e1 : (n == 2) ? e2 : e3;
        g_w[m * 4 + n] = ev * inv;
    }
}

// ---------------------------------------------------------------------------
// K4: R7 gconv (best measured). block = (4 t's, n); 256 thr = 4 grp x 64 c.
// Expert mix in-block; AS rows pad 26 (LDS.64 pairs, broadcast);
// staged coalesced input and output through buf.
// ---------------------------------------------------------------------------
__global__ __launch_bounds__(256, 4)
void gconv_kernel(const float* __restrict__ x, const float* __restrict__ A,
                  float* __restrict__ out) {
    __shared__ __align__(16) float ASs[4][650];   // 10.4 KB
    __shared__ float buf[64 * 101];               // 25.9 KB (xs then os)
    const int tid = threadIdx.x;
    const int n   = blockIdx.y;
    const int t0  = blockIdx.x * 4;

    const float w0 = g_w[n * 4 + 0];
    const float w1 = g_w[n * 4 + 1];
    const float w2 = g_w[n * 4 + 2];
    const float w3 = g_w[n * 4 + 3];

    // Phase 0: mixed adjacency (A[e,t,v,w] at (e*128 + t)*625)
    for (int idx = tid; idx < 2500; idx += 256) {
        const int grp = idx / 625;
        const int j   = idx - grp * 625;
        const int v   = j / 25;
        const int ww  = j - v * 25;
        const float* At = A + (t0 + grp) * 625 + j;
        ASs[grp][v * 26 + ww] = w0 * At[0]
                              + w1 * At[1 * 128 * 625]
                              + w2 * At[2 * 128 * 625]
                              + w3 * At[3 * 128 * 625];
    }

    // Phase 1: xs stage (coalesced 100-float runs per c)
    const float* xb = x + n * K_DIM + t0 * 25;
#pragma unroll
    for (int u = 0; u < 25; u++) {
        const int idx = u * 256 + tid;                 // 0..6399
        const int c = idx / 100;
        const int j = idx - c * 100;                   // grp*25 + v (contiguous)
        const int grp = j / 25;
        const int v   = j - grp * 25;
        buf[grp * 1600 + c * 25 + v] = xb[c * 3200 + j];
    }
    __syncthreads();

    const int grp = tid >> 6;
    const int c   = tid & 63;

    float rx[25];
    {
        const float* xr = &buf[grp * 1600 + c * 25];
#pragma unroll
        for (int v = 0; v < 25; v++) rx[v] = xr[v];
    }

    const float* Ab = &ASs[grp][0];
    u64 acc2[12];
#pragma unroll
    for (int p = 0; p < 12; p++) acc2[p] = 0ull;
    float acc24 = 0.0f;

#pragma unroll
    for (int v = 0; v < 25; v++) {
        const float gv = rx[v];
        const u64 gr = pack2(gv, gv);
        const float* row = Ab + v * 26;
#pragma unroll
        for (int p = 0; p < 12; p++) ffma2(acc2[p], gr, *(const u64*)(row + 2 * p));
        acc24 += gv * row[24];
    }

    __syncthreads();   // done reading xs; reuse buf as os

    {
        float* os = &buf[c * 101 + grp * 25];
#pragma unroll
        for (int p = 0; p < 12; p++) {
            float lo, hi;
            unpack2(acc2[p], lo, hi);
            os[2 * p] = lo; os[2 * p + 1] = hi;
        }
        os[24] = acc24;
    }
    __syncthreads();

    // Phase 3: coalesced output
    float* ob = out + n * K_DIM + t0 * 25;
#pragma unroll
    for (int u = 0; u < 25; u++) {
        const int idx = u * 256 + tid;
        const int c2 = idx / 100;
        const int j  = idx - c2 * 100;
        ob[c2 * 3200 + j] = buf[c2 * 101 + j];
    }
}

// ---------------------------------------------------------------------------
extern "C" void kernel_launch(void* const* d_in, const int* in_sizes, int n_in,
                              void* d_out, int out_size) {
    const float* x  = (const float*)d_in[0];
    const float* W0 = (const float*)d_in[1];
    const float* b0 = (const float*)d_in[2];
    const float* W1 = (const float*)d_in[3];
    const float* b1 = (const float*)d_in[4];
    const float* W2 = (const float*)d_in[5];
    const float* b2 = (const float*)d_in[6];
    const float* A  = (const float*)d_in[7];
    float* out = (float*)d_out;

    cudaFuncSetAttribute(gemm0_mma, cudaFuncAttributeMaxDynamicSharedMemorySize,
                         SMEM_WORDS * 4);

    gemm0_mma<<<SPLIT, 256, SMEM_WORDS * 4>>>(x, W0);
    reduce_kernel<<<256, 256>>>(b0);
    gating_kernel<<<M_DIM, 256>>>(W1, b1, W2, b2);
    gconv_kernel<<<dim3(32, 32), 256>>>(x, A, out);
}

// round 11
// speedup vs baseline: 1.5087x; 1.0267x over previous
#include <cuda_runtime.h>
#include <cuda_bf16.h>
#include <cstdint>

// ---------------------------------------------------------------------------
// ConvTemporalGraphical — smem-staged bf16-split mma.sync GEMM with register
// software pipeline (prefetch next tile's LDGs under current tile's MMAs).
// K2: reduce 296 partials + b0 + ELU -> h0
// K3: gating fused
// K4: gconv (R7/R10 version — best measured)
// ---------------------------------------------------------------------------

#define K_DIM 204800
#define M_DIM 32
#define N_DIM 256
#define SPLIT 296              // = 2 * 148 SMs
#define TILES_TOTAL 6400       // K / 32

__device__ float g_partial[SPLIT * M_DIM * N_DIM];   // 9.7 MB
__device__ float g_h0[M_DIM * N_DIM];
__device__ float g_w[M_DIM * 4];

typedef unsigned long long u64;

__device__ __forceinline__ float elu(float v) { return v > 0.0f ? v : expm1f(v); }

__device__ __forceinline__ u64 pack2(float lo, float hi) {
    u64 r; asm("mov.b64 %0, {%1, %2};" : "=l"(r) : "f"(lo), "f"(hi)); return r;
}
__device__ __forceinline__ void unpack2(u64 v, float& lo, float& hi) {
    asm("mov.b64 {%0, %1}, %2;" : "=f"(lo), "=f"(hi) : "l"(v));
}
__device__ __forceinline__ void ffma2(u64& d, u64 a, u64 b) {
    asm("fma.rn.f32x2 %0, %1, %2, %0;" : "+l"(d) : "l"(a), "l"(b));
}

// split (a,b) into bf16x2 hi and bf16x2 lo (residual)
__device__ __forceinline__ void split2(float a, float b, uint32_t& hi, uint32_t& lo) {
    __nv_bfloat162 h = __floats2bfloat162_rn(a, b);
    hi = *reinterpret_cast<uint32_t*>(&h);
    const float ra = a - __bfloat162float(h.x);
    const float rb = b - __bfloat162float(h.y);
    __nv_bfloat162 l = __floats2bfloat162_rn(ra, rb);
    lo = *reinterpret_cast<uint32_t*>(&l);
}

__device__ __forceinline__ void mma_bf16(float* d, const uint32_t* a,
                                         uint32_t b0, uint32_t b1) {
    asm volatile(
        "mma.sync.aligned.m16n8k16.row.col.f32.bf16.bf16.f32 "
        "{%0,%1,%2,%3}, {%4,%5,%6,%7}, {%8,%9}, {%0,%1,%2,%3};"
        : "+f"(d[0]), "+f"(d[1]), "+f"(d[2]), "+f"(d[3])
        : "r"(a[0]), "r"(a[1]), "r"(a[2]), "r"(a[3]), "r"(b0), "r"(b1));
}

// smem word strides: rows ≡ 8 mod 32 -> fragment banks 8*tg+g all distinct.
#define BPAD 264
#define APAD 40
#define OFF_BH 0
#define OFF_BL (16 * BPAD)
#define OFF_AH (32 * BPAD)
#define OFF_AL (32 * BPAD + 16 * APAD)
#define SMEM_WORDS (32 * BPAD + 32 * APAD)

// ---------------------------------------------------------------------------
// K1: per tile: sync; split+STS regs->smem; sync; LDG next tile -> regs;
// compute current tile's 48 MMAs (LDG latency hidden under MMAs).
// ---------------------------------------------------------------------------
__global__ __launch_bounds__(256, 2)
void gemm0_mma(const float* __restrict__ x, const float* __restrict__ W0) {
    extern __shared__ uint32_t sm[];
    uint32_t* Bh  = sm + OFF_BH;
    uint32_t* Bl  = sm + OFF_BL;
    uint32_t* Ahs = sm + OFF_AH;
    uint32_t* Als = sm + OFF_AL;

    const int tid  = threadIdx.x;
    const int w    = tid >> 5;
    const int lane = tid & 31;
    const int g    = lane >> 2;    // 0..7
    const int tg   = lane & 3;     // 0..3
    const int nbase = w * 32;

    const int tl_beg = (int)(((long)blockIdx.x       * TILES_TOTAL) / SPLIT);
    const int tl_end = (int)(((long)(blockIdx.x + 1) * TILES_TOTAL) / SPLIT);

    // loader mappings (fixed per thread)
    const int bkp[4] = { (0*256+tid) >> 6, (1*256+tid) >> 6, (2*256+tid) >> 6, (3*256+tid) >> 6 };
    const int bqn[4] = { ((0*256+tid) & 63) * 4, ((1*256+tid) & 63) * 4,
                         ((2*256+tid) & 63) * 4, ((3*256+tid) & 63) * 4 };
    const int am[2]  = { (0*256+tid) >> 4, (1*256+tid) >> 4 };
    const int akp[2] = { (0*256+tid) & 15, (1*256+tid) & 15 };

    float d[2][4][4];
#pragma unroll
    for (int mt = 0; mt < 2; mt++)
#pragma unroll
        for (int j = 0; j < 4; j++)
#pragma unroll
            for (int r = 0; r < 4; r++) d[mt][j][r] = 0.0f;

    float4 br[4][2];   // prefetched W0 rows
    float2 ar[2];      // prefetched x pairs

    // prologue: load first tile into regs
    {
        const int kb = tl_beg * 32;
#pragma unroll
        for (int it = 0; it < 4; it++) {
            br[it][0] = *(const float4*)(W0 + (long)(kb + 2 * bkp[it])     * N_DIM + bqn[it]);
            br[it][1] = *(const float4*)(W0 + (long)(kb + 2 * bkp[it] + 1) * N_DIM + bqn[it]);
        }
#pragma unroll
        for (int it = 0; it < 2; it++)
            ar[it] = *(const float2*)(x + (long)am[it] * K_DIM + kb + 2 * akp[it]);
    }

    for (int tl = tl_beg; tl < tl_end; tl++) {
        __syncthreads();   // previous tile's smem reads complete

        // ---- split + store current tile (from regs) ----
#pragma unroll
        for (int it = 0; it < 4; it++) {
            uint32_t h[4], l[4];
            split2(br[it][0].x, br[it][1].x, h[0], l[0]);
            split2(br[it][0].y, br[it][1].y, h[1], l[1]);
            split2(br[it][0].z, br[it][1].z, h[2], l[2]);
            split2(br[it][0].w, br[it][1].w, h[3], l[3]);
            *(uint4*)&Bh[bkp[it] * BPAD + bqn[it]] = make_uint4(h[0], h[1], h[2], h[3]);
            *(uint4*)&Bl[bkp[it] * BPAD + bqn[it]] = make_uint4(l[0], l[1], l[2], l[3]);
        }
#pragma unroll
        for (int it = 0; it < 2; it++) {
            uint32_t h, l;
            split2(ar[it].x, ar[it].y, h, l);
            Ahs[akp[it] * APAD + am[it]] = h;
            Als[akp[it] * APAD + am[it]] = l;
        }
        __syncthreads();

        // ---- issue next tile's loads (latency hidden under MMAs below) ----
        if (tl + 1 < tl_end) {
            const int kb = (tl + 1) * 32;
#pragma unroll
            for (int it = 0; it < 4; it++) {
                br[it][0] = *(const float4*)(W0 + (long)(kb + 2 * bkp[it])     * N_DIM + bqn[it]);
                br[it][1] = *(const float4*)(W0 + (long)(kb + 2 * bkp[it] + 1) * N_DIM + bqn[it]);
            }
#pragma unroll
            for (int it = 0; it < 2; it++)
                ar[it] = *(const float2*)(x + (long)am[it] * K_DIM + kb + 2 * akp[it]);
        }

        // ---- compute current tile: 2 ksteps x 24 MMAs ----
#pragma unroll
        for (int s = 0; s < 2; s++) {
            const int kp0 = s * 8 + tg;
            const int kp1 = kp0 + 4;

            uint32_t ah[2][4], al[2][4];
#pragma unroll
            for (int mt = 0; mt < 2; mt++) {
                const int m0 = mt * 16 + g;
                ah[mt][0] = Ahs[kp0 * APAD + m0];
                ah[mt][1] = Ahs[kp0 * APAD + m0 + 8];
                ah[mt][2] = Ahs[kp1 * APAD + m0];
                ah[mt][3] = Ahs[kp1 * APAD + m0 + 8];
                al[mt][0] = Als[kp0 * APAD + m0];
                al[mt][1] = Als[kp0 * APAD + m0 + 8];
                al[mt][2] = Als[kp1 * APAD + m0];
                al[mt][3] = Als[kp1 * APAD + m0 + 8];
            }
#pragma unroll
            for (int j = 0; j < 4; j++) {
                const int n = nbase + j * 8 + g;
                const uint32_t bh0 = Bh[kp0 * BPAD + n];
                const uint32_t bh1 = Bh[kp1 * BPAD + n];
                const uint32_t bl0 = Bl[kp0 * BPAD + n];
                const uint32_t bl1 = Bl[kp1 * BPAD + n];
#pragma unroll
                for (int mt = 0; mt < 2; mt++) {
                    mma_bf16(d[mt][j], ah[mt], bh0, bh1);
                    mma_bf16(d[mt][j], ah[mt], bl0, bl1);
                    mma_bf16(d[mt][j], al[mt], bh0, bh1);
                }
            }
        }
    }

    float* po = g_partial + blockIdx.x * (M_DIM * N_DIM);
#pragma unroll
    for (int mt = 0; mt < 2; mt++) {
#pragma unroll
        for (int j = 0; j < 4; j++) {
            const int m0 = mt * 16 + g;
            const int n0 = nbase + j * 8 + 2 * tg;
            *(float2*)(po + m0 * N_DIM + n0)       = make_float2(d[mt][j][0], d[mt][j][1]);
            *(float2*)(po + (m0 + 8) * N_DIM + n0) = make_float2(d[mt][j][2], d[mt][j][3]);
        }
    }
}

// ---------------------------------------------------------------------------
// K2: reduce 296 partials (fixed order -> deterministic) + b0 + ELU.
// ---------------------------------------------------------------------------
__global__ __launch_bounds__(256)
void reduce_kernel(const float* __restrict__ b0) {
    __shared__ float red[8][32];
    const int m  = blockIdx.x >> 3;
    const int nc = (blockIdx.x & 7) * 32;
    const int nl = threadIdx.x & 31;
    const int sl = threadIdx.x >> 5;
    const int n  = nc + nl;

    float s = 0.0f;
    const float* p = g_partial + (sl * 37) * (M_DIM * N_DIM) + m * N_DIM + n;
#pragma unroll
    for (int i = 0; i < 37; i++) s += p[i * (M_DIM * N_DIM)];
    red[sl][nl] = s;
    __syncthreads();
    if (sl == 0) {
        float a = b0[n];
#pragma unroll
        for (int j = 0; j < 8; j++) a += red[j][nl];
        g_h0[m * N_DIM + n] = elu(a);
    }
}

// ---------------------------------------------------------------------------
// K3: fused gating; W1 loop with 4 independent accumulator chains.
// ---------------------------------------------------------------------------
__global__ __launch_bounds__(256)
void gating_kernel(const float* __restrict__ W1, const float* __restrict__ b1,
                   const float* __restrict__ W2, const float* __restrict__ b2) {
    __shared__ float hs[256];
    __shared__ float h1s[256];
    __shared__ float lg[4];
    const int m = blockIdx.x;
    const int n = threadIdx.x;

    hs[n] = g_h0[m * N_DIM + n];
    __syncthreads();

    float a0 = 0.0f, a1 = 0.0f, a2 = 0.0f, a3 = 0.0f;
#pragma unroll 8
    for (int k = 0; k < 64; k++) {
        a0 += hs[k]       * W1[k * 256 + n];
        a1 += hs[k + 64]  * W1[(k + 64) * 256 + n];
        a2 += hs[k + 128] * W1[(k + 128) * 256 + n];
        a3 += hs[k + 192] * W1[(k + 192) * 256 + n];
    }
    h1s[n] = elu(b1[n] + (a0 + a1) + (a2 + a3));
    __syncthreads();

    const int w = n >> 5, lane = n & 31;
    if (w < 4) {
        float s = 0.0f;
#pragma unroll
        for (int k = lane; k < 256; k += 32) s += h1s[k] * W2[k * 4 + w];
#pragma unroll
        for (int o = 16; o; o >>= 1) s += __shfl_xor_sync(0xffffffffu, s, o);
        if (lane == 0) lg[w] = s + b2[w];
    }
    __syncthreads();

    if (n < 4) {
        const float l0 = lg[0], l1 = lg[1], l2 = lg[2], l3 = lg[3];
        const float mx = fmaxf(fmaxf(l0, l1), fmaxf(l2, l3));
        const float e0 = expf(l0 - mx), e1 = expf(l1 - mx);
        const float e2 = expf(l2 - mx), e3 = expf(l3 - mx);
        const float inv = 1.0f / (e0 + e1 + e2 + e3);
        const float ev = (n == 0) ? e0 : (n == 1) ? e1 : (n == 2) ? e2 : e3;
        g_w[m * 4 + n] = ev * inv;
    }
}

// ---------------------------------------------------------------------------
// K4: gconv (R7/R10 best). block = (4 t's, n); 256 thr = 4 grp x 64 c.
// ---------------------------------------------------------------------------
__global__ __launch_bounds__(256, 4)
void gconv_kernel(const float* __restrict__ x, const float* __restrict__ A,
                  float* __restrict__ out) {
    __shared__ __align__(16) float ASs[4][650];   // 10.4 KB
    __shared__ float buf[64 * 101];               // 25.9 KB (xs then os)
    const int tid = threadIdx.x;
    const int n   = blockIdx.y;
    const int t0  = blockIdx.x * 4;

    const float w0 = g_w[n * 4 + 0];
    const float w1 = g_w[n * 4 + 1];
    const float w2 = g_w[n * 4 + 2];
    const float w3 = g_w[n * 4 + 3];

    for (int idx = tid; idx < 2500; idx += 256) {
        const int grp = idx / 625;
        const int j   = idx - grp * 625;
        const int v   = j / 25;
        const int ww  = j - v * 25;
        const float* At = A + (t0 + grp) * 625 + j;
        ASs[grp][v * 26 + ww] = w0 * At[0]
                              + w1 * At[1 * 128 * 625]
                              + w2 * At[2 * 128 * 625]
                              + w3 * At[3 * 128 * 625];
    }

    const float* xb = x + n * K_DIM + t0 * 25;
#pragma unroll
    for (int u = 0; u < 25; u++) {
        const int idx = u * 256 + tid;
        const int c = idx / 100;
        const int j = idx - c * 100;
        const int grp = j / 25;
        const int v   = j - grp * 25;
        buf[grp * 1600 + c * 25 + v] = xb[c * 3200 + j];
    }
    __syncthreads();

    const int grp = tid >> 6;
    const int c   = tid & 63;

    float rx[25];
    {
        const float* xr = &buf[grp * 1600 + c * 25];
#pragma unroll
        for (int v = 0; v < 25; v++) rx[v] = xr[v];
    }

    const float* Ab = &ASs[grp][0];
    u64 acc2[12];
#pragma unroll
    for (int p = 0; p < 12; p++) acc2[p] = 0ull;
    float acc24 = 0.0f;

#pragma unroll
    for (int v = 0; v < 25; v++) {
        const float gv = rx[v];
        const u64 gr = pack2(gv, gv);
        const float* row = Ab + v * 26;
#pragma unroll
        for (int p = 0; p < 12; p++) ffma2(acc2[p], gr, *(const u64*)(row + 2 * p));
        acc24 += gv * row[24];
    }

    __syncthreads();

    {
        float* os = &buf[c * 101 + grp * 25];
#pragma unroll
        for (int p = 0; p < 12; p++) {
            float lo, hi;
            unpack2(acc2[p], lo, hi);
            os[2 * p] = lo; os[2 * p + 1] = hi;
        }
        os[24] = acc24;
    }
    __syncthreads();

    float* ob = out + n * K_DIM + t0 * 25;
#pragma unroll
    for (int u = 0; u < 25; u++) {
        const int idx = u * 256 + tid;
        const int c2 = idx / 100;
        const int j  = idx - c2 * 100;
        ob[c2 * 3200 + j] = buf[c2 * 101 + j];
    }
}

// ---------------------------------------------------------------------------
extern "C" void kernel_launch(void* const* d_in, const int* in_sizes, int n_in,
                              void* d_out, int out_size) {
    const float* x  = (const float*)d_in[0];
    const float* W0 = (const float*)d_in[1];
    const float* b0 = (const float*)d_in[2];
    const float* W1 = (const float*)d_in[3];
    const float* b1 = (const float*)d_in[4];
    const float* W2 = (const float*)d_in[5];
    const float* b2 = (const float*)d_in[6];
    const float* A  = (const float*)d_in[7];
    float* out = (float*)d_out;

    cudaFuncSetAttribute(gemm0_mma, cudaFuncAttributeMaxDynamicSharedMemorySize,
                         SMEM_WORDS * 4);

    gemm0_mma<<<SPLIT, 256, SMEM_WORDS * 4>>>(x, W0);
    reduce_kernel<<<256, 256>>>(b0);
    gating_kernel<<<M_DIM, 256>>>(W1, b1, W2, b2);
    gconv_kernel<<<dim3(32, 32), 256>>>(x, A, out);
}

// round 12
// speedup vs baseline: 1.6617x; 1.1014x over previous
#include <cuda_runtime.h>
#include <cuda_bf16.h>
#include <cstdint>

// ---------------------------------------------------------------------------
// ConvTemporalGraphical
// K1: bf16-split mma.sync GEMM, 3-stage cp.async pipeline for W0 tiles
//     (raw fp32 staged; split conversion fused into compute phase).
// K2: reduce 296 partials + b0 + ELU -> h0
// K3: fused gating
// K4: gconv, 2 channels per thread (halved broadcast-LDS per output)
// ---------------------------------------------------------------------------

#define K_DIM 204800
#define M_DIM 32
#define N_DIM 256
#define SPLIT 296              // = 2 * 148 SMs
#define TILES_TOTAL 6400       // K / 32

__device__ float g_partial[SPLIT * M_DIM * N_DIM];   // 9.7 MB
__device__ float g_h0[M_DIM * N_DIM];
__device__ float g_w[M_DIM * 4];

typedef unsigned long long u64;

__device__ __forceinline__ float elu(float v) { return v > 0.0f ? v : expm1f(v); }

__device__ __forceinline__ u64 pack2(float lo, float hi) {
    u64 r; asm("mov.b64 %0, {%1, %2};" : "=l"(r) : "f"(lo), "f"(hi)); return r;
}
__device__ __forceinline__ void unpack2(u64 v, float& lo, float& hi) {
    asm("mov.b64 {%0, %1}, %2;" : "=f"(lo), "=f"(hi) : "l"(v));
}
__device__ __forceinline__ void ffma2(u64& d, u64 a, u64 b) {
    asm("fma.rn.f32x2 %0, %1, %2, %0;" : "+l"(d) : "l"(a), "l"(b));
}
__device__ __forceinline__ uint32_t smem_u32(const void* p) {
    uint32_t a;
    asm("{ .reg .u64 t; cvta.to.shared.u64 t, %1; cvt.u32.u64 %0, t; }" : "=r"(a) : "l"(p));
    return a;
}

// split (a,b) into bf16x2 hi and bf16x2 lo (residual)
__device__ __forceinline__ void split2(float a, float b, uint32_t& hi, uint32_t& lo) {
    __nv_bfloat162 h = __floats2bfloat162_rn(a, b);
    hi = *reinterpret_cast<uint32_t*>(&h);
    const float ra = a - __bfloat162float(h.x);
    const float rb = b - __bfloat162float(h.y);
    __nv_bfloat162 l = __floats2bfloat162_rn(ra, rb);
    lo = *reinterpret_cast<uint32_t*>(&l);
}

__device__ __forceinline__ void mma_bf16(float* d, const uint32_t* a,
                                         uint32_t b0, uint32_t b1) {
    asm volatile(
        "mma.sync.aligned.m16n8k16.row.col.f32.bf16.bf16.f32 "
        "{%0,%1,%2,%3}, {%4,%5,%6,%7}, {%8,%9}, {%0,%1,%2,%3};"
        : "+f"(d[0]), "+f"(d[1]), "+f"(d[2]), "+f"(d[3])
        : "r"(a[0]), "r"(a[1]), "r"(a[2]), "r"(a[3]), "r"(b0), "r"(b1));
}

// smem layout (fp32 words)
#define BPADW 260                      // 260 % 32 == 4 -> frag banks 2tg*4+g distinct
#define BSTW  (32 * BPADW)             // 8320 words per B stage
#define NSTG  3
#define AOFFW (NSTG * BSTW)            // 24960
#define APAD  40                       // 40 % 32 == 8 -> banks tg*8+g distinct
#define ASTW  (2 * 16 * APAD)          // Ah + Al per stage = 1280 words
#define SMEM_WORDS (AOFFW + 2 * ASTW)  // 27520 words = 110080 B

// ---------------------------------------------------------------------------
// K1: 3-stage cp.async pipeline. Per iter: wait_group 1; sync; issue B(i+2);
// STS A(i+1) (from regs); LDG A(i+2); compute(i) with in-loop bf16 split.
// ---------------------------------------------------------------------------
__global__ __launch_bounds__(256, 2)
void gemm0_mma(const float* __restrict__ x, const float* __restrict__ W0) {
    extern __shared__ uint32_t sm[];
    const uint32_t sb = smem_u32(sm);

    const int tid  = threadIdx.x;
    const int w    = tid >> 5;
    const int lane = tid & 31;
    const int g    = lane >> 2;    // 0..7
    const int tg   = lane & 3;     // 0..3
    const int nbase = w * 32;

    const int tl_beg = (int)(((long)blockIdx.x       * TILES_TOTAL) / SPLIT);
    const int tl_end = (int)(((long)(blockIdx.x + 1) * TILES_TOTAL) / SPLIT);
    const int T = tl_end - tl_beg;   // 21 or 22

    // A loader mapping
    const int am[2]  = { (0*256+tid) >> 4, (1*256+tid) >> 4 };
    const int akp[2] = { (0*256+tid) & 15, (1*256+tid) & 15 };

    float d[2][4][4];
#pragma unroll
    for (int mt = 0; mt < 2; mt++)
#pragma unroll
        for (int j = 0; j < 4; j++)
#pragma unroll
            for (int r = 0; r < 4; r++) d[mt][j][r] = 0.0f;

    // B issue: 8 x 16B chunks per thread per tile
    auto issueB = [&](int tl, int slot) {
        const float* gsrc = W0 + (long)tl * 32 * N_DIM;
        const uint32_t sdst = sb + (uint32_t)(slot * BSTW) * 4u;
#pragma unroll
        for (int it = 0; it < 8; it++) {
            const int id  = it * 256 + tid;
            const int row = id >> 6;
            const int col = (id & 63) * 4;
            const uint32_t dst = sdst + (uint32_t)(row * BPADW + col) * 4u;
            const float* src = gsrc + row * N_DIM + col;
            asm volatile("cp.async.cg.shared.global [%0], [%1], 16;"
                         :: "r"(dst), "l"(src));
        }
    };

    float2 ar[2];
    auto ldgA = [&](int tl) {
#pragma unroll
        for (int it = 0; it < 2; it++)
            ar[it] = *(const float2*)(x + (long)am[it] * K_DIM + tl * 32 + 2 * akp[it]);
    };
    auto stsA = [&](int slot) {
        uint32_t* Ah = sm + AOFFW + slot * ASTW;
        uint32_t* Al = Ah + 16 * APAD;
#pragma unroll
        for (int it = 0; it < 2; it++) {
            uint32_t h, l;
            split2(ar[it].x, ar[it].y, h, l);
            Ah[akp[it] * APAD + am[it]] = h;
            Al[akp[it] * APAD + am[it]] = l;
        }
    };

    // prologue: B stages 0,1 in flight; A stage 0 stored, A tile 1 in regs
    issueB(tl_beg, 0);
    asm volatile("cp.async.commit_group;");
    issueB(tl_beg + 1, 1);
    asm volatile("cp.async.commit_group;");
    ldgA(tl_beg);
    stsA(0);
    ldgA(tl_beg + 1);

    for (int i = 0; i < T; i++) {
        asm volatile("cp.async.wait_group 1;");
        __syncthreads();   // B(i) + A(i) visible; all warps past compute(i-1)

        if (i + 2 < T) issueB(tl_beg + i + 2, (i + 2) % NSTG);
        asm volatile("cp.async.commit_group;");
        if (i + 1 < T) stsA((i + 1) & 1);
        if (i + 2 < T) ldgA(tl_beg + i + 2);

        // ---- compute tile i ----
        const float*    Bb = (const float*)(sm) + (i % NSTG) * BSTW;
        const uint32_t* Ah = sm + AOFFW + (i & 1) * ASTW;
        const uint32_t* Al = Ah + 16 * APAD;

#pragma unroll
        for (int s = 0; s < 2; s++) {
            const int kp0 = s * 8 + tg;
            const int kp1 = kp0 + 4;

            uint32_t ah[2][4], al[2][4];
#pragma unroll
            for (int mt = 0; mt < 2; mt++) {
                const int m0 = mt * 16 + g;
                ah[mt][0] = Ah[kp0 * APAD + m0];
                ah[mt][1] = Ah[kp0 * APAD + m0 + 8];
                ah[mt][2] = Ah[kp1 * APAD + m0];
                ah[mt][3] = Ah[kp1 * APAD + m0 + 8];
                al[mt][0] = Al[kp0 * APAD + m0];
                al[mt][1] = Al[kp0 * APAD + m0 + 8];
                al[mt][2] = Al[kp1 * APAD + m0];
                al[mt][3] = Al[kp1 * APAD + m0 + 8];
            }
#pragma unroll
            for (int j = 0; j < 4; j++) {
                const int n = nbase + j * 8 + g;
                const int kr0 = 2 * kp0;          // tile rows 16s+2tg
                const int kr1 = 2 * kp1;          // 16s+2tg+8
                const float v00 = Bb[kr0 * BPADW + n];
                const float v01 = Bb[(kr0 + 1) * BPADW + n];
                const float v10 = Bb[kr1 * BPADW + n];
                const float v11 = Bb[(kr1 + 1) * BPADW + n];
                uint32_t bh0, bl0, bh1, bl1;
                split2(v00, v01, bh0, bl0);
                split2(v10, v11, bh1, bl1);
#pragma unroll
                for (int mt = 0; mt < 2; mt++) {
                    mma_bf16(d[mt][j], ah[mt], bh0, bh1);
                    mma_bf16(d[mt][j], ah[mt], bl0, bl1);
                    mma_bf16(d[mt][j], al[mt], bh0, bh1);
                }
            }
        }
    }

    float* po = g_partial + blockIdx.x * (M_DIM * N_DIM);
#pragma unroll
    for (int mt = 0; mt < 2; mt++) {
#pragma unroll
        for (int j = 0; j < 4; j++) {
            const int m0 = mt * 16 + g;
            const int n0 = nbase + j * 8 + 2 * tg;
            *(float2*)(po + m0 * N_DIM + n0)       = make_float2(d[mt][j][0], d[mt][j][1]);
            *(float2*)(po + (m0 + 8) * N_DIM + n0) = make_float2(d[mt][j][2], d[mt][j][3]);
        }
    }
}

// ---------------------------------------------------------------------------
// K2: reduce 296 partials (fixed order -> deterministic) + b0 + ELU.
// ---------------------------------------------------------------------------
__global__ __launch_bounds__(256)
void reduce_kernel(const float* __restrict__ b0) {
    __shared__ float red[8][32];
    const int m  = blockIdx.x >> 3;
    const int nc = (blockIdx.x & 7) * 32;
    const int nl = threadIdx.x & 31;
    const int sl = threadIdx.x >> 5;
    const int n  = nc + nl;

    float s = 0.0f;
    const float* p = g_partial + (sl * 37) * (M_DIM * N_DIM) + m * N_DIM + n;
#pragma unroll
    for (int i = 0; i < 37; i++) s += p[i * (M_DIM * N_DIM)];
    red[sl][nl] = s;
    __syncthreads();
    if (sl == 0) {
        float a = b0[n];
#pragma unroll
        for (int j = 0; j < 8; j++) a += red[j][nl];
        g_h0[m * N_DIM + n] = elu(a);
    }
}

// ---------------------------------------------------------------------------
// K3: fused gating; W1 loop with 4 independent accumulator chains.
// ---------------------------------------------------------------------------
__global__ __launch_bounds__(256)
void gating_kernel(const float* __restrict__ W1, const float* __restrict__ b1,
                   const float* __restrict__ W2, const float* __restrict__ b2) {
    __shared__ float hs[256];
    __shared__ float h1s[256];
    __shared__ float lg[4];
    const int m = blockIdx.x;
    const int n = threadIdx.x;

    hs[n] = g_h0[m * N_DIM + n];
    __syncthreads();

    float a0 = 0.0f, a1 = 0.0f, a2 = 0.0f, a3 = 0.0f;
#pragma unroll 8
    for (int k = 0; k < 64; k++) {
        a0 += hs[k]       * W1[k * 256 + n];
        a1 += hs[k + 64]  * W1[(k + 64) * 256 + n];
        a2 += hs[k + 128] * W1[(k + 128) * 256 + n];
        a3 += hs[k + 192] * W1[(k + 192) * 256 + n];
    }
    h1s[n] = elu(b1[n] + (a0 + a1) + (a2 + a3));
    __syncthreads();

    const int w = n >> 5, lane = n & 31;
    if (w < 4) {
        float s = 0.0f;
#pragma unroll
        for (int k = lane; k < 256; k += 32) s += h1s[k] * W2[k * 4 + w];
#pragma unroll
        for (int o = 16; o; o >>= 1) s += __shfl_xor_sync(0xffffffffu, s, o);
        if (lane == 0) lg[w] = s + b2[w];
    }
    __syncthreads();

    if (n < 4) {
        const float l0 = lg[0], l1 = lg[1], l2 = lg[2], l3 = lg[3];
        const float mx = fmaxf(fmaxf(l0, l1), fmaxf(l2, l3));
        const float e0 = expf(l0 - mx), e1 = expf(l1 - mx);
        const float e2 = expf(l2 - mx), e3 = expf(l3 - mx);
        const float inv = 1.0f / (e0 + e1 + e2 + e3);
        const float ev = (n == 0) ? e0 : (n == 1) ? e1 : (n == 2) ? e2 : e3;
        g_w[m * 4 + n] = ev * inv;
    }
}

// ---------------------------------------------------------------------------
// K4: gconv, 2 channels per thread. Block = 128 thr = 4 warps (one per t);
// lane c0 handles channels c0 and c0+32: each broadcast AS-row LDS.64 feeds
// two ffma2 -> compute-phase L1 wavefronts nearly halved vs 1c/thread.
// ---------------------------------------------------------------------------
__global__ __launch_bounds__(128)
void gconv_kernel(const float* __restrict__ x, const float* __restrict__ A,
                  float* __restrict__ out) {
    __shared__ __align__(16) float ASs[4][650];   // 10.4 KB
    __shared__ float buf[64 * 101];               // 25.9 KB (xs then os)
    const int tid = threadIdx.x;
    const int n   = blockIdx.y;
    const int t0  = blockIdx.x * 4;

    const float w0 = g_w[n * 4 + 0];
    const float w1 = g_w[n * 4 + 1];
    const float w2 = g_w[n * 4 + 2];
    const float w3 = g_w[n * 4 + 3];

    // Phase 0: expert mix
    for (int idx = tid; idx < 2500; idx += 128) {
        const int grp = idx / 625;
        const int j   = idx - grp * 625;
        const int v   = j / 25;
        const int ww  = j - v * 25;
        const float* At = A + (t0 + grp) * 625 + j;
        ASs[grp][v * 26 + ww] = w0 * At[0]
                              + w1 * At[1 * 128 * 625]
                              + w2 * At[2 * 128 * 625]
                              + w3 * At[3 * 128 * 625];
    }

    // Phase 1: xs stage (coalesced 100-float runs per c)
    const float* xb = x + n * K_DIM + t0 * 25;
#pragma unroll 10
    for (int u = 0; u < 50; u++) {
        const int idx = u * 128 + tid;                 // 0..6399
        const int c = idx / 100;
        const int j = idx - c * 100;                   // grp*25 + v
        const int grp = j / 25;
        const int v   = j - grp * 25;
        buf[grp * 1600 + c * 25 + v] = xb[c * 3200 + j];
    }
    __syncthreads();

    const int grp = tid >> 5;       // warp = t group
    const int c0  = tid & 31;       // channels c0 and c0+32
    const float* xg = &buf[grp * 1600];
    const float* Ab = &ASs[grp][0];

    u64 accA[12], accB[12];
#pragma unroll
    for (int p = 0; p < 12; p++) { accA[p] = 0ull; accB[p] = 0ull; }
    float a24 = 0.0f, b24 = 0.0f;

#pragma unroll
    for (int v = 0; v < 25; v++) {
        const float x0 = xg[c0 * 25 + v];
        const float x1 = xg[(c0 + 32) * 25 + v];
        const u64 g0 = pack2(x0, x0);
        const u64 g1 = pack2(x1, x1);
        const float* row = Ab + v * 26;
#pragma unroll
        for (int p = 0; p < 12; p++) {
            const u64 wv = *(const u64*)(row + 2 * p);
            ffma2(accA[p], g0, wv);
            ffma2(accB[p], g1, wv);
        }
        const float aw = row[24];
        a24 += x0 * aw;
        b24 += x1 * aw;
    }

    __syncthreads();   // done reading xs; reuse buf as os

    {
        float* osA = &buf[c0 * 101 + grp * 25];
        float* osB = &buf[(c0 + 32) * 101 + grp * 25];
#pragma unroll
        for (int p = 0; p < 12; p++) {
            float lo, hi;
            unpack2(accA[p], lo, hi);
            osA[2 * p] = lo; osA[2 * p + 1] = hi;
            unpack2(accB[p], lo, hi);
            osB[2 * p] = lo; osB[2 * p + 1] = hi;
        }
        osA[24] = a24;
        osB[24] = b24;
    }
    __syncthreads();

    // Phase 3: coalesced output
    float* ob = out + n * K_DIM + t0 * 25;
#pragma unroll 10
    for (int u = 0; u < 50; u++) {
        const int idx = u * 128 + tid;
        const int c2 = idx / 100;
        const int j  = idx - c2 * 100;
        ob[c2 * 3200 + j] = buf[c2 * 101 + j];
    }
}

// ---------------------------------------------------------------------------
extern "C" void kernel_launch(void* const* d_in, const int* in_sizes, int n_in,
                              void* d_out, int out_size) {
    const float* x  = (const float*)d_in[0];
    const float* W0 = (const float*)d_in[1];
    const float* b0 = (const float*)d_in[2];
    const float* W1 = (const float*)d_in[3];
    const float* b1 = (const float*)d_in[4];
    const float* W2 = (const float*)d_in[5];
    const float* b2 = (const float*)d_in[6];
    const float* A  = (const float*)d_in[7];
    float* out = (float*)d_out;

    cudaFuncSetAttribute(gemm0_mma, cudaFuncAttributeMaxDynamicSharedMemorySize,
                         SMEM_WORDS * 4);

    gemm0_mma<<<SPLIT, 256, SMEM_WORDS * 4>>>(x, W0);
    reduce_kernel<<<256, 256>>>(b0);
    gating_kernel<<<M_DIM, 256>>>(W1, b1, W2, b2);
    gconv_kernel<<<dim3(32, 32), 128>>>(x, A, out);
}

// round 13
// speedup vs baseline: 1.6895x; 1.0168x over previous
#include <cuda_runtime.h>
#include <cuda_fp16.h>
#include <cstdint>

// ---------------------------------------------------------------------------
// ConvTemporalGraphical
// K1: fp16 2-term mma.sync GEMM (x split hi/lo fp16, W0 single fp16 plane),
//     3-stage cp.async pipeline for raw fp32 W0 tiles.
//     x@W0 ~= (xh+xl)@fp16(W0); dropped term x@(W0-fp16(W0)) ~ 2^-12 rel.
// K2: reduce 296 partials + b0 + ELU -> h0
// K3: fused gating
// K4: gconv, 2 channels per thread (R12 best)
// ---------------------------------------------------------------------------

#define K_DIM 204800
#define M_DIM 32
#define N_DIM 256
#define SPLIT 296              // = 2 * 148 SMs
#define TILES_TOTAL 6400       // K / 32

__device__ float g_partial[SPLIT * M_DIM * N_DIM];   // 9.7 MB
__device__ float g_h0[M_DIM * N_DIM];
__device__ float g_w[M_DIM * 4];

typedef unsigned long long u64;

__device__ __forceinline__ float elu(float v) { return v > 0.0f ? v : expm1f(v); }

__device__ __forceinline__ u64 pack2(float lo, float hi) {
    u64 r; asm("mov.b64 %0, {%1, %2};" : "=l"(r) : "f"(lo), "f"(hi)); return r;
}
__device__ __forceinline__ void unpack2(u64 v, float& lo, float& hi) {
    asm("mov.b64 {%0, %1}, %2;" : "=f"(lo), "=f"(hi) : "l"(v));
}
__device__ __forceinline__ void ffma2(u64& d, u64 a, u64 b) {
    asm("fma.rn.f32x2 %0, %1, %2, %0;" : "+l"(d) : "l"(a), "l"(b));
}
__device__ __forceinline__ uint32_t smem_u32(const void* p) {
    uint32_t a;
    asm("{ .reg .u64 t; cvta.to.shared.u64 t, %1; cvt.u32.u64 %0, t; }" : "=r"(a) : "l"(p));
    return a;
}

// fp16 pack of (a,b)
__device__ __forceinline__ uint32_t packh2(float a, float b) {
    __half2 h = __floats2half2_rn(a, b);
    return *reinterpret_cast<uint32_t*>(&h);
}
// fp16 split of (a,b): hi = fp16(a,b), lo = fp16 residual
__device__ __forceinline__ void split2h(float a, float b, uint32_t& hi, uint32_t& lo) {
    __half2 h = __floats2half2_rn(a, b);
    hi = *reinterpret_cast<uint32_t*>(&h);
    float2 hf = __half22float2(h);
    __half2 l = __floats2half2_rn(a - hf.x, b - hf.y);
    lo = *reinterpret_cast<uint32_t*>(&l);
}

__device__ __forceinline__ void mma_f16(float* d, const uint32_t* a,
                                        uint32_t b0, uint32_t b1) {
    asm volatile(
        "mma.sync.aligned.m16n8k16.row.col.f32.f16.f16.f32 "
        "{%0,%1,%2,%3}, {%4,%5,%6,%7}, {%8,%9}, {%0,%1,%2,%3};"
        : "+f"(d[0]), "+f"(d[1]), "+f"(d[2]), "+f"(d[3])
        : "r"(a[0]), "r"(a[1]), "r"(a[2]), "r"(a[3]), "r"(b0), "r"(b1));
}

// smem layout (fp32 words)
#define BPADW 260                      // 260 % 32 == 4 -> frag banks distinct
#define BSTW  (32 * BPADW)             // 8320 words per B stage
#define NSTG  3
#define AOFFW (NSTG * BSTW)            // 24960
#define APAD  40                       // 40 % 32 == 8 -> frag banks distinct
#define ASTW  (2 * 16 * APAD)          // Ah + Al per stage = 1280 words
#define SMEM_WORDS (AOFFW + 2 * ASTW)  // 27520 words = 110080 B

// ---------------------------------------------------------------------------
// K1: 3-stage cp.async pipeline; fp16 2-term compute.
// Per iter: wait_group 1; sync; issue B(i+2); STS A(i+1); LDG A(i+2);
// compute(i): per kstep 16 A-LDS + 16 B-LDS + 8 cvt + 16 MMA.
// ---------------------------------------------------------------------------
__global__ __launch_bounds__(256, 2)
void gemm0_mma(const float* __restrict__ x, const float* __restrict__ W0) {
    extern __shared__ uint32_t sm[];
    const uint32_t sb = smem_u32(sm);

    const int tid  = threadIdx.x;
    const int w    = tid >> 5;
    const int lane = tid & 31;
    const int g    = lane >> 2;    // 0..7
    const int tg   = lane & 3;     // 0..3
    const int nbase = w * 32;

    const int tl_beg = (int)(((long)blockIdx.x       * TILES_TOTAL) / SPLIT);
    const int tl_end = (int)(((long)(blockIdx.x + 1) * TILES_TOTAL) / SPLIT);
    const int T = tl_end - tl_beg;   // 21 or 22

    // A loader mapping
    const int am[2]  = { (0*256+tid) >> 4, (1*256+tid) >> 4 };
    const int akp[2] = { (0*256+tid) & 15, (1*256+tid) & 15 };

    float d[2][4][4];
#pragma unroll
    for (int mt = 0; mt < 2; mt++)
#pragma unroll
        for (int j = 0; j < 4; j++)
#pragma unroll
            for (int r = 0; r < 4; r++) d[mt][j][r] = 0.0f;

    // B issue: 8 x 16B chunks per thread per tile
    auto issueB = [&](int tl, int slot) {
        const float* gsrc = W0 + (long)tl * 32 * N_DIM;
        const uint32_t sdst = sb + (uint32_t)(slot * BSTW) * 4u;
#pragma unroll
        for (int it = 0; it < 8; it++) {
            const int id  = it * 256 + tid;
            const int row = id >> 6;
            const int col = (id & 63) * 4;
            const uint32_t dst = sdst + (uint32_t)(row * BPADW + col) * 4u;
            const float* src = gsrc + row * N_DIM + col;
            asm volatile("cp.async.cg.shared.global [%0], [%1], 16;"
                         :: "r"(dst), "l"(src));
        }
    };

    float2 ar[2];
    auto ldgA = [&](int tl) {
#pragma unroll
        for (int it = 0; it < 2; it++)
            ar[it] = *(const float2*)(x + (long)am[it] * K_DIM + tl * 32 + 2 * akp[it]);
    };
    auto stsA = [&](int slot) {
        uint32_t* Ah = sm + AOFFW + slot * ASTW;
        uint32_t* Al = Ah + 16 * APAD;
#pragma unroll
        for (int it = 0; it < 2; it++) {
            uint32_t h, l;
            split2h(ar[it].x, ar[it].y, h, l);
            Ah[akp[it] * APAD + am[it]] = h;
            Al[akp[it] * APAD + am[it]] = l;
        }
    };

    // prologue
    issueB(tl_beg, 0);
    asm volatile("cp.async.commit_group;");
    issueB(tl_beg + 1, 1);
    asm volatile("cp.async.commit_group;");
    ldgA(tl_beg);
    stsA(0);
    ldgA(tl_beg + 1);

    for (int i = 0; i < T; i++) {
        asm volatile("cp.async.wait_group 1;");
        __syncthreads();

        if (i + 2 < T) issueB(tl_beg + i + 2, (i + 2) % NSTG);
        asm volatile("cp.async.commit_group;");
        if (i + 1 < T) stsA((i + 1) & 1);
        if (i + 2 < T) ldgA(tl_beg + i + 2);

        // ---- compute tile i ----
        const float*    Bb = (const float*)(sm) + (i % NSTG) * BSTW;
        const uint32_t* Ah = sm + AOFFW + (i & 1) * ASTW;
        const uint32_t* Al = Ah + 16 * APAD;

#pragma unroll
        for (int s = 0; s < 2; s++) {
            const int kp0 = s * 8 + tg;
            const int kp1 = kp0 + 4;

            uint32_t ah[2][4], al[2][4];
#pragma unroll
            for (int mt = 0; mt < 2; mt++) {
                const int m0 = mt * 16 + g;
                ah[mt][0] = Ah[kp0 * APAD + m0];
                ah[mt][1] = Ah[kp0 * APAD + m0 + 8];
                ah[mt][2] = Ah[kp1 * APAD + m0];
                ah[mt][3] = Ah[kp1 * APAD + m0 + 8];
                al[mt][0] = Al[kp0 * APAD + m0];
                al[mt][1] = Al[kp0 * APAD + m0 + 8];
                al[mt][2] = Al[kp1 * APAD + m0];
                al[mt][3] = Al[kp1 * APAD + m0 + 8];
            }

            // B fragments for all 4 n-tiles (single fp16 plane)
            uint32_t bh[4][2];
#pragma unroll
            for (int j = 0; j < 4; j++) {
                const int n = nbase + j * 8 + g;
                const int kr0 = 2 * kp0;
                const int kr1 = 2 * kp1;
                const float v00 = Bb[kr0 * BPADW + n];
                const float v01 = Bb[(kr0 + 1) * BPADW + n];
                const float v10 = Bb[kr1 * BPADW + n];
                const float v11 = Bb[(kr1 + 1) * BPADW + n];
                bh[j][0] = packh2(v00, v01);
                bh[j][1] = packh2(v10, v11);
            }

            // term 1: Ah * B  (8 independent accumulators)
#pragma unroll
            for (int j = 0; j < 4; j++)
#pragma unroll
                for (int mt = 0; mt < 2; mt++)
                    mma_f16(d[mt][j], ah[mt], bh[j][0], bh[j][1]);
            // term 2: Al * B
#pragma unroll
            for (int j = 0; j < 4; j++)
#pragma unroll
                for (int mt = 0; mt < 2; mt++)
                    mma_f16(d[mt][j], al[mt], bh[j][0], bh[j][1]);
        }
    }

    float* po = g_partial + blockIdx.x * (M_DIM * N_DIM);
#pragma unroll
    for (int mt = 0; mt < 2; mt++) {
#pragma unroll
        for (int j = 0; j < 4; j++) {
            const int m0 = mt * 16 + g;
            const int n0 = nbase + j * 8 + 2 * tg;
            *(float2*)(po + m0 * N_DIM + n0)       = make_float2(d[mt][j][0], d[mt][j][1]);
            *(float2*)(po + (m0 + 8) * N_DIM + n0) = make_float2(d[mt][j][2], d[mt][j][3]);
        }
    }
}

// ---------------------------------------------------------------------------
// K2: reduce 296 partials (fixed order -> deterministic) + b0 + ELU.
// ---------------------------------------------------------------------------
__global__ __launch_bounds__(256)
void reduce_kernel(const float* __restrict__ b0) {
    __shared__ float red[8][32];
    const int m  = blockIdx.x >> 3;
    const int nc = (blockIdx.x & 7) * 32;
    const int nl = threadIdx.x & 31;
    const int sl = threadIdx.x >> 5;
    const int n  = nc + nl;

    float s = 0.0f;
    const float* p = g_partial + (sl * 37) * (M_DIM * N_DIM) + m * N_DIM + n;
#pragma unroll
    for (int i = 0; i < 37; i++) s += p[i * (M_DIM * N_DIM)];
    red[sl][nl] = s;
    __syncthreads();
    if (sl == 0) {
        float a = b0[n];
#pragma unroll
        for (int j = 0; j < 8; j++) a += red[j][nl];
        g_h0[m * N_DIM + n] = elu(a);
    }
}

// ---------------------------------------------------------------------------
// K3: fused gating; W1 loop with 4 independent accumulator chains.
// ---------------------------------------------------------------------------
__global__ __launch_bounds__(256)
void gating_kernel(const float* __restrict__ W1, const float* __restrict__ b1,
                   const float* __restrict__ W2, const float* __restrict__ b2) {
    __shared__ float hs[256];
    __shared__ float h1s[256];
    __shared__ float lg[4];
    const int m = blockIdx.x;
    const int n = threadIdx.x;

    hs[n] = g_h0[m * N_DIM + n];
    __syncthreads();

    float a0 = 0.0f, a1 = 0.0f, a2 = 0.0f, a3 = 0.0f;
#pragma unroll 8
    for (int k = 0; k < 64; k++) {
        a0 += hs[k]       * W1[k * 256 + n];
        a1 += hs[k + 64]  * W1[(k + 64) * 256 + n];
        a2 += hs[k + 128] * W1[(k + 128) * 256 + n];
        a3 += hs[k + 192] * W1[(k + 192) * 256 + n];
    }
    h1s[n] = elu(b1[n] + (a0 + a1) + (a2 + a3));
    __syncthreads();

    const int w = n >> 5, lane = n & 31;
    if (w < 4) {
        float s = 0.0f;
#pragma unroll
        for (int k = lane; k < 256; k += 32) s += h1s[k] * W2[k * 4 + w];
#pragma unroll
        for (int o = 16; o; o >>= 1) s += __shfl_xor_sync(0xffffffffu, s, o);
        if (lane == 0) lg[w] = s + b2[w];
    }
    __syncthreads();

    if (n < 4) {
        const float l0 = lg[0], l1 = lg[1], l2 = lg[2], l3 = lg[3];
        const float mx = fmaxf(fmaxf(l0, l1), fmaxf(l2, l3));
        const float e0 = expf(l0 - mx), e1 = expf(l1 - mx);
        const float e2 = expf(l2 - mx), e3 = expf(l3 - mx);
        const float inv = 1.0f / (e0 + e1 + e2 + e3);
        const float ev = (n == 0) ? e0 : (n == 1) ? e1 : (n == 2) ? e2 : e3;
        g_w[m * 4 + n] = ev * inv;
    }
}

// ---------------------------------------------------------------------------
// K4: gconv, 2 channels per thread (R12 best, unchanged).
// ---------------------------------------------------------------------------
__global__ __launch_bounds__(128)
void gconv_kernel(const float* __restrict__ x, const float* __restrict__ A,
                  float* __restrict__ out) {
    __shared__ __align__(16) float ASs[4][650];   // 10.4 KB
    __shared__ float buf[64 * 101];               // 25.9 KB (xs then os)
    const int tid = threadIdx.x;
    const int n   = blockIdx.y;
    const int t0  = blockIdx.x * 4;

    const float w0 = g_w[n * 4 + 0];
    const float w1 = g_w[n * 4 + 1];
    const float w2 = g_w[n * 4 + 2];
    const float w3 = g_w[n * 4 + 3];

    for (int idx = tid; idx < 2500; idx += 128) {
        const int grp = idx / 625;
        const int j   = idx - grp * 625;
        const int v   = j / 25;
        const int ww  = j - v * 25;
        const float* At = A + (t0 + grp) * 625 + j;
        ASs[grp][v * 26 + ww] = w0 * At[0]
                              + w1 * At[1 * 128 * 625]
                              + w2 * At[2 * 128 * 625]
                              + w3 * At[3 * 128 * 625];
    }

    const float* xb = x + n * K_DIM + t0 * 25;
#pragma unroll 10
    for (int u = 0; u < 50; u++) {
        const int idx = u * 128 + tid;
        const int c = idx / 100;
        const int j = idx - c * 100;
        const int grp = j / 25;
        const int v   = j - grp * 25;
        buf[grp * 1600 + c * 25 + v] = xb[c * 3200 + j];
    }
    __syncthreads();

    const int grp = tid >> 5;
    const int c0  = tid & 31;
    const float* xg = &buf[grp * 1600];
    const float* Ab = &ASs[grp][0];

    u64 accA[12], accB[12];
#pragma unroll
    for (int p = 0; p < 12; p++) { accA[p] = 0ull; accB[p] = 0ull; }
    float a24 = 0.0f, b24 = 0.0f;

#pragma unroll
    for (int v = 0; v < 25; v++) {
        const float x0 = xg[c0 * 25 + v];
        const float x1 = xg[(c0 + 32) * 25 + v];
        const u64 g0 = pack2(x0, x0);
        const u64 g1 = pack2(x1, x1);
        const float* row = Ab + v * 26;
#pragma unroll
        for (int p = 0; p < 12; p++) {
            const u64 wv = *(const u64*)(row + 2 * p);
            ffma2(accA[p], g0, wv);
            ffma2(accB[p], g1, wv);
        }
        const float aw = row[24];
        a24 += x0 * aw;
        b24 += x1 * aw;
    }

    __syncthreads();

    {
        float* osA = &buf[c0 * 101 + grp * 25];
        float* osB = &buf[(c0 + 32) * 101 + grp * 25];
#pragma unroll
        for (int p = 0; p < 12; p++) {
            float lo, hi;
            unpack2(accA[p], lo, hi);
            osA[2 * p] = lo; osA[2 * p + 1] = hi;
            unpack2(accB[p], lo, hi);
            osB[2 * p] = lo; osB[2 * p + 1] = hi;
        }
        osA[24] = a24;
        osB[24] = b24;
    }
    __syncthreads();

    float* ob = out + n * K_DIM + t0 * 25;
#pragma unroll 10
    for (int u = 0; u < 50; u++) {
        const int idx = u * 128 + tid;
        const int c2 = idx / 100;
        const int j  = idx - c2 * 100;
        ob[c2 * 3200 + j] = buf[c2 * 101 + j];
    }
}

// ---------------------------------------------------------------------------
extern "C" void kernel_launch(void* const* d_in, const int* in_sizes, int n_in,
                              void* d_out, int out_size) {
    const float* x  = (const float*)d_in[0];
    const float* W0 = (const float*)d_in[1];
    const float* b0 = (const float*)d_in[2];
    const float* W1 = (const float*)d_in[3];
    const float* b1 = (const float*)d_in[4];
    const float* W2 = (const float*)d_in[5];
    const float* b2 = (const float*)d_in[6];
    const float* A  = (const float*)d_in[7];
    float* out = (float*)d_out;

    cudaFuncSetAttribute(gemm0_mma, cudaFuncAttributeMaxDynamicSharedMemorySize,
                         SMEM_WORDS * 4);

    gemm0_mma<<<SPLIT, 256, SMEM_WORDS * 4>>>(x, W0);
    reduce_kernel<<<256, 256>>>(b0);
    gating_kernel<<<M_DIM, 256>>>(W1, b1, W2, b2);
    gconv_kernel<<<dim3(32, 32), 128>>>(x, A, out);
}

// round 14
// speedup vs baseline: 1.7894x; 1.0591x over previous
#include <cuda_runtime.h>
#include <cuda_fp16.h>
#include <cstdint>

// ---------------------------------------------------------------------------
// ConvTemporalGraphical
// K1: fp16 2-term mma.sync GEMM (x split hi/lo fp16, W0 single fp16 plane),
//     cp.async 3-stage pipeline; B frags via column-permuted LDS.128,
//     A frags via kp-pair LDS.64.
// K2: reduce 296 partials + b0 + ELU -> h0
// K3a: h1 = ELU(h0@W1+b1)  (256 blocks)
// K3b: softmax(h1@W2+b2) -> w[32,4]  (32 blocks)
// K4: gconv, 2 channels per thread (R12 best, unchanged)
// ---------------------------------------------------------------------------

#define K_DIM 204800
#define M_DIM 32
#define N_DIM 256
#define SPLIT 296              // = 2 * 148 SMs
#define TILES_TOTAL 6400       // K / 32

__device__ float g_partial[SPLIT * M_DIM * N_DIM];   // 9.7 MB
__device__ float g_h0[M_DIM * N_DIM];
__device__ float g_h1[M_DIM * N_DIM];
__device__ float g_w[M_DIM * 4];

typedef unsigned long long u64;

__device__ __forceinline__ float elu(float v) { return v > 0.0f ? v : expm1f(v); }

__device__ __forceinline__ u64 pack2(float lo, float hi) {
    u64 r; asm("mov.b64 %0, {%1, %2};" : "=l"(r) : "f"(lo), "f"(hi)); return r;
}
__device__ __forceinline__ void unpack2(u64 v, float& lo, float& hi) {
    asm("mov.b64 {%0, %1}, %2;" : "=f"(lo), "=f"(hi) : "l"(v));
}
__device__ __forceinline__ void ffma2(u64& d, u64 a, u64 b) {
    asm("fma.rn.f32x2 %0, %1, %2, %0;" : "+l"(d) : "l"(a), "l"(b));
}
__device__ __forceinline__ uint32_t smem_u32(const void* p) {
    uint32_t a;
    asm("{ .reg .u64 t; cvta.to.shared.u64 t, %1; cvt.u32.u64 %0, t; }" : "=r"(a) : "l"(p));
    return a;
}
__device__ __forceinline__ uint32_t packh2(float a, float b) {
    __half2 h = __floats2half2_rn(a, b);
    return *reinterpret_cast<uint32_t*>(&h);
}
__device__ __forceinline__ void split2h(float a, float b, uint32_t& hi, uint32_t& lo) {
    __half2 h = __floats2half2_rn(a, b);
    hi = *reinterpret_cast<uint32_t*>(&h);
    float2 hf = __half22float2(h);
    __half2 l = __floats2half2_rn(a - hf.x, b - hf.y);
    lo = *reinterpret_cast<uint32_t*>(&l);
}
__device__ __forceinline__ void mma_f16(float* d, const uint32_t* a,
                                        uint32_t b0, uint32_t b1) {
    asm volatile(
        "mma.sync.aligned.m16n8k16.row.col.f32.f16.f16.f32 "
        "{%0,%1,%2,%3}, {%4,%5,%6,%7}, {%8,%9}, {%0,%1,%2,%3};"
        : "+f"(d[0]), "+f"(d[1]), "+f"(d[2]), "+f"(d[3])
        : "r"(a[0]), "r"(a[1]), "r"(a[2]), "r"(a[3]), "r"(b0), "r"(b1));
}

// smem layout (fp32 words)
#define BPADW 260                      // 260 % 16 == 4 -> permuted frag banks ok
#define BSTW  (32 * BPADW)             // 8320 words per B stage
#define NSTG  3
#define AOFFW (NSTG * BSTW)            // 24960
#define AMP   36                       // A pair-row m-stride (uint2 units)
#define APLW  (8 * AMP * 2)            // words per A plane = 576
#define ASTW2 (2 * APLW)               // hi+lo per stage = 1152 words
#define SMEM_WORDS (AOFFW + 2 * ASTW2) // 27264 words = 109056 B

// ---------------------------------------------------------------------------
// K1: cp.async 3-stage pipeline; fp16 2-term compute.
// B frag trick: warp tile j covers logical cols {nbase + 4g + j}, so one
// LDS.128 per row serves all 4 j's. A stored as (kp,kp+4) uint2 pairs.
// ---------------------------------------------------------------------------
__global__ __launch_bounds__(256, 2)
void gemm0_mma(const float* __restrict__ x, const float* __restrict__ W0) {
    extern __shared__ uint32_t sm[];
    const uint32_t sb = smem_u32(sm);

    const int tid  = threadIdx.x;
    const int w    = tid >> 5;
    const int lane = tid & 31;
    const int g    = lane >> 2;    // 0..7
    const int tg   = lane & 3;     // 0..3
    const int nbase = w * 32;

    const int tl_beg = (int)(((long)blockIdx.x       * TILES_TOTAL) / SPLIT);
    const int tl_end = (int)(((long)(blockIdx.x + 1) * TILES_TOTAL) / SPLIT);
    const int T = tl_end - tl_beg;   // 21 or 22

    // A loader mapping: 2 tasks/thread, task id -> (m, kp)
    const int am[2]  = { (0*256+tid) >> 4, (1*256+tid) >> 4 };
    const int akp[2] = { (0*256+tid) & 15, (1*256+tid) & 15 };

    float d[2][4][4];
#pragma unroll
    for (int mt = 0; mt < 2; mt++)
#pragma unroll
        for (int j = 0; j < 4; j++)
#pragma unroll
            for (int r = 0; r < 4; r++) d[mt][j][r] = 0.0f;

    auto issueB = [&](int tl, int slot) {
        const float* gsrc = W0 + (long)tl * 32 * N_DIM;
        const uint32_t sdst = sb + (uint32_t)(slot * BSTW) * 4u;
#pragma unroll
        for (int it = 0; it < 8; it++) {
            const int id  = it * 256 + tid;
            const int row = id >> 6;
            const int col = (id & 63) * 4;
            const uint32_t dst = sdst + (uint32_t)(row * BPADW + col) * 4u;
            const float* src = gsrc + row * N_DIM + col;
            asm volatile("cp.async.cg.shared.global [%0], [%1], 16;"
                         :: "r"(dst), "l"(src));
        }
    };

    float2 ar[2];
    auto ldgA = [&](int tl) {
#pragma unroll
        for (int it = 0; it < 2; it++)
            ar[it] = *(const float2*)(x + (long)am[it] * K_DIM + tl * 32 + 2 * akp[it]);
    };
    // A pair layout: plane[q][m] uint2 = {kp = s*8+tq (word0), kp+4 (word1)},
    // q = s*4 + tq.
    auto stsA = [&](int slot) {
        uint32_t* Ah = sm + AOFFW + slot * ASTW2;
        uint32_t* Al = Ah + APLW;
#pragma unroll
        for (int it = 0; it < 2; it++) {
            uint32_t h, l;
            split2h(ar[it].x, ar[it].y, h, l);
            const int kp = akp[it];
            const int s_ = kp >> 3;
            const int tq = kp & 3;
            const int hf = (kp >> 2) & 1;
            const int widx = ((s_ * 4 + tq) * AMP + am[it]) * 2 + hf;
            Ah[widx] = h;
            Al[widx] = l;
        }
    };

    // prologue
    issueB(tl_beg, 0);
    asm volatile("cp.async.commit_group;");
    issueB(tl_beg + 1, 1);
    asm volatile("cp.async.commit_group;");
    ldgA(tl_beg);
    stsA(0);
    ldgA(tl_beg + 1);

    for (int i = 0; i < T; i++) {
        asm volatile("cp.async.wait_group 1;");
        __syncthreads();

        if (i + 2 < T) issueB(tl_beg + i + 2, (i + 2) % NSTG);
        asm volatile("cp.async.commit_group;");
        if (i + 1 < T) stsA((i + 1) & 1);
        if (i + 2 < T) ldgA(tl_beg + i + 2);

        // ---- compute tile i ----
        const float*    Bb = (const float*)(sm) + (i % NSTG) * BSTW;
        const uint32_t* Ah = sm + AOFFW + (i & 1) * ASTW2;
        const uint32_t* Al = Ah + APLW;

#pragma unroll
        for (int s = 0; s < 2; s++) {
            const int q  = s * 4 + tg;          // pair index: kp0=s*8+tg, kp1=kp0+4
            const int kp0 = s * 8 + tg;

            // A fragments: 2 LDS.64 per (mt, plane)
            uint32_t ah[2][4], al[2][4];
#pragma unroll
            for (int mt = 0; mt < 2; mt++) {
                const int m0 = mt * 16 + g;
                const uint2 pa0 = *(const uint2*)(Ah + (q * AMP + m0) * 2);
                const uint2 pa1 = *(const uint2*)(Ah + (q * AMP + m0 + 8) * 2);
                ah[mt][0] = pa0.x; ah[mt][2] = pa0.y;
                ah[mt][1] = pa1.x; ah[mt][3] = pa1.y;
                const uint2 pl0 = *(const uint2*)(Al + (q * AMP + m0) * 2);
                const uint2 pl1 = *(const uint2*)(Al + (q * AMP + m0 + 8) * 2);
                al[mt][0] = pl0.x; al[mt][2] = pl0.y;
                al[mt][1] = pl1.x; al[mt][3] = pl1.y;
            }

            // B fragments: 4 LDS.128 (rows kr0, kr0+1, kr1, kr1+1; cols 4g..4g+3)
            const int kr0 = 2 * kp0;
            const int kr1 = kr0 + 8;
            const float4 r0 = *(const float4*)(Bb + kr0 * BPADW + nbase + 4 * g);
            const float4 r1 = *(const float4*)(Bb + (kr0 + 1) * BPADW + nbase + 4 * g);
            const float4 r2 = *(const float4*)(Bb + kr1 * BPADW + nbase + 4 * g);
            const float4 r3 = *(const float4*)(Bb + (kr1 + 1) * BPADW + nbase + 4 * g);
            uint32_t bh[4][2];
            bh[0][0] = packh2(r0.x, r1.x); bh[0][1] = packh2(r2.x, r3.x);
            bh[1][0] = packh2(r0.y, r1.y); bh[1][1] = packh2(r2.y, r3.y);
            bh[2][0] = packh2(r0.z, r1.z); bh[2][1] = packh2(r2.z, r3.z);
            bh[3][0] = packh2(r0.w, r1.w); bh[3][1] = packh2(r2.w, r3.w);

            // term 1: Ah * B
#pragma unroll
            for (int j = 0; j < 4; j++)
#pragma unroll
                for (int mt = 0; mt < 2; mt++)
                    mma_f16(d[mt][j], ah[mt], bh[j][0], bh[j][1]);
            // term 2: Al * B
#pragma unroll
            for (int j = 0; j < 4; j++)
#pragma unroll
                for (int mt = 0; mt < 2; mt++)
                    mma_f16(d[mt][j], al[mt], bh[j][0], bh[j][1]);
        }
    }

    // epilogue: tile j col-in-tile (2tg+delta) -> logical n = 4*(2tg+delta)+j
    float* po = g_partial + blockIdx.x * (M_DIM * N_DIM);
#pragma unroll
    for (int mt = 0; mt < 2; mt++) {
#pragma unroll
        for (int j = 0; j < 4; j++) {
            const int m0 = mt * 16 + g;
            const int c0 = nbase + 8 * tg + j;
            po[m0 * N_DIM + c0]           = d[mt][j][0];
            po[m0 * N_DIM + c0 + 4]       = d[mt][j][1];
            po[(m0 + 8) * N_DIM + c0]     = d[mt][j][2];
            po[(m0 + 8) * N_DIM + c0 + 4] = d[mt][j][3];
        }
    }
}

// ---------------------------------------------------------------------------
// K2: reduce 296 partials (fixed order -> deterministic) + b0 + ELU.
// ---------------------------------------------------------------------------
__global__ __launch_bounds__(256)
void reduce_kernel(const float* __restrict__ b0) {
    __shared__ float red[8][32];
    const int m  = blockIdx.x >> 3;
    const int nc = (blockIdx.x & 7) * 32;
    const int nl = threadIdx.x & 31;
    const int sl = threadIdx.x >> 5;
    const int n  = nc + nl;

    float s = 0.0f;
    const float* p = g_partial + (sl * 37) * (M_DIM * N_DIM) + m * N_DIM + n;
#pragma unroll
    for (int i = 0; i < 37; i++) s += p[i * (M_DIM * N_DIM)];
    red[sl][nl] = s;
    __syncthreads();
    if (sl == 0) {
        float a = b0[n];
#pragma unroll
        for (int j = 0; j < 8; j++) a += red[j][nl];
        g_h0[m * N_DIM + n] = elu(a);
    }
}

// ---------------------------------------------------------------------------
// K3a: h1 = ELU(h0 @ W1 + b1). 256 blocks: (m, 32-wide n chunk).
// thread (nl, sl): k-slice partial, smem reduce.
// ---------------------------------------------------------------------------
__global__ __launch_bounds__(256)
void mlp1_kernel(const float* __restrict__ W1, const float* __restrict__ b1) {
    __shared__ float red[8][32];
    const int m  = blockIdx.x >> 3;
    const int nc = (blockIdx.x & 7) * 32;
    const int nl = threadIdx.x & 31;
    const int sl = threadIdx.x >> 5;
    const int n  = nc + nl;

    float s = 0.0f;
    const float* hr = g_h0 + m * N_DIM;
#pragma unroll
    for (int k = 0; k < 32; k++)
        s += hr[sl * 32 + k] * W1[(sl * 32 + k) * 256 + n];
    red[sl][nl] = s;
    __syncthreads();
    if (sl == 0) {
        float a = b1[n];
#pragma unroll
        for (int j = 0; j < 8; j++) a += red[j][nl];
        g_h1[m * N_DIM + n] = elu(a);
    }
}

// ---------------------------------------------------------------------------
// K3b: logits + softmax. 32 blocks (one per m), 128 thr: warp = expert e,
// lanes k-split; shfl reduce; softmax on threads 0..3.
// ---------------------------------------------------------------------------
__global__ __launch_bounds__(128)
void softmax_kernel(const float* __restrict__ W2, const float* __restrict__ b2) {
    __shared__ float lg[4];
    const int m    = blockIdx.x;
    const int e    = threadIdx.x >> 5;
    const int lane = threadIdx.x & 31;

    float s = 0.0f;
    const float* hr = g_h1 + m * N_DIM;
#pragma unroll
    for (int k = lane; k < 256; k += 32) s += hr[k] * W2[k * 4 + e];
#pragma unroll
    for (int o = 16; o; o >>= 1) s += __shfl_xor_sync(0xffffffffu, s, o);
    if (lane == 0) lg[e] = s + b2[e];
    __syncthreads();

    if (threadIdx.x < 4) {
        const float l0 = lg[0], l1 = lg[1], l2 = lg[2], l3 = lg[3];
        const float mx = fmaxf(fmaxf(l0, l1), fmaxf(l2, l3));
        const float e0 = expf(l0 - mx), e1 = expf(l1 - mx);
        const float e2 = expf(l2 - mx), e3 = expf(l3 - mx);
        const float inv = 1.0f / (e0 + e1 + e2 + e3);
        const float ev = (threadIdx.x == 0) ? e0 : (threadIdx.x == 1) ? e1
                       : (threadIdx.x == 2) ? e2 : e3;
        g_w[m * 4 + threadIdx.x] = ev * inv;
    }
}

// ---------------------------------------------------------------------------
// K4: gconv, 2 channels per thread (R12 best, unchanged).
// ---------------------------------------------------------------------------
__global__ __launch_bounds__(128)
void gconv_kernel(const float* __restrict__ x, const float* __restrict__ A,
                  float* __restrict__ out) {
    __shared__ __align__(16) float ASs[4][650];   // 10.4 KB
    __shared__ float buf[64 * 101];               // 25.9 KB (xs then os)
    const int tid = threadIdx.x;
    const int n   = blockIdx.y;
    const int t0  = blockIdx.x * 4;

    const float w0 = g_w[n * 4 + 0];
    const float w1 = g_w[n * 4 + 1];
    const float w2 = g_w[n * 4 + 2];
    const float w3 = g_w[n * 4 + 3];

    for (int idx = tid; idx < 2500; idx += 128) {
        const int grp = idx / 625;
        const int j   = idx - grp * 625;
        const int v   = j / 25;
        const int ww  = j - v * 25;
        const float* At = A + (t0 + grp) * 625 + j;
        ASs[grp][v * 26 + ww] = w0 * At[0]
                              + w1 * At[1 * 128 * 625]
                              + w2 * At[2 * 128 * 625]
                              + w3 * At[3 * 128 * 625];
    }

    const float* xb = x + n * K_DIM + t0 * 25;
#pragma unroll 10
    for (int u = 0; u < 50; u++) {
        const int idx = u * 128 + tid;
        const int c = idx / 100;
        const int j = idx - c * 100;
        const int grp = j / 25;
        const int v   = j - grp * 25;
        buf[grp * 1600 + c * 25 + v] = xb[c * 3200 + j];
    }
    __syncthreads();

    const int grp = tid >> 5;
    const int c0  = tid & 31;
    const float* xg = &buf[grp * 1600];
    const float* Ab = &ASs[grp][0];

    u64 accA[12], accB[12];
#pragma unroll
    for (int p = 0; p < 12; p++) { accA[p] = 0ull; accB[p] = 0ull; }
    float a24 = 0.0f, b24 = 0.0f;

#pragma unroll
    for (int v = 0; v < 25; v++) {
        const float x0 = xg[c0 * 25 + v];
        const float x1 = xg[(c0 + 32) * 25 + v];
        const u64 g0 = pack2(x0, x0);
        const u64 g1 = pack2(x1, x1);
        const float* row = Ab + v * 26;
#pragma unroll
        for (int p = 0; p < 12; p++) {
            const u64 wv = *(const u64*)(row + 2 * p);
            ffma2(accA[p], g0, wv);
            ffma2(accB[p], g1, wv);
        }
        const float aw = row[24];
        a24 += x0 * aw;
        b24 += x1 * aw;
    }

    __syncthreads();

    {
        float* osA = &buf[c0 * 101 + grp * 25];
        float* osB = &buf[(c0 + 32) * 101 + grp * 25];
#pragma unroll
        for (int p = 0; p < 12; p++) {
            float lo, hi;
            unpack2(accA[p], lo, hi);
            osA[2 * p] = lo; osA[2 * p + 1] = hi;
            unpack2(accB[p], lo, hi);
            osB[2 * p] = lo; osB[2 * p + 1] = hi;
        }
        osA[24] = a24;
        osB[24] = b24;
    }
    __syncthreads();

    float* ob = out + n * K_DIM + t0 * 25;
#pragma unroll 10
    for (int u = 0; u < 50; u++) {
        const int idx = u * 128 + tid;
        const int c2 = idx / 100;
        const int j  = idx - c2 * 100;
        ob[c2 * 3200 + j] = buf[c2 * 101 + j];
    }
}

// ---------------------------------------------------------------------------
extern "C" void kernel_launch(void* const* d_in, const int* in_sizes, int n_in,
                              void* d_out, int out_size) {
    const float* x  = (const float*)d_in[0];
    const float* W0 = (const float*)d_in[1];
    const float* b0 = (const float*)d_in[2];
    const float* W1 = (const float*)d_in[3];
    const float* b1 = (const float*)d_in[4];
    const float* W2 = (const float*)d_in[5];
    const float* b2 = (const float*)d_in[6];
    const float* A  = (const float*)d_in[7];
    float* out = (float*)d_out;

    cudaFuncSetAttribute(gemm0_mma, cudaFuncAttributeMaxDynamicSharedMemorySize,
                         SMEM_WORDS * 4);

    gemm0_mma<<<SPLIT, 256, SMEM_WORDS * 4>>>(x, W0);
    reduce_kernel<<<256, 256>>>(b0);
    mlp1_kernel<<<256, 256>>>(W1, b1);
    softmax_kernel<<<32, 128>>>(W2, b2);
    gconv_kernel<<<dim3(32, 32), 128>>>(x, A, out);
}

// round 15
// speedup vs baseline: 1.8399x; 1.0282x over previous
#include <cuda_runtime.h>
#include <cuda_fp16.h>
#include <cstdint>

// ---------------------------------------------------------------------------
// ConvTemporalGraphical
// K1: fp16 1-term mma.sync GEMM (x and W0 both fp16-rounded; error ~5e-5),
//     cp.async 3-stage pipeline; B frags column-permuted LDS.128,
//     A frags kp-pair LDS.64.
// K2: reduce 296 partials + b0 + ELU -> h0
// K3: h1 = ELU(h0@W1+b1)  (256 blocks)
// K4: gconv with fused logits+softmax prologue, 2 channels per thread.
// ---------------------------------------------------------------------------

#define K_DIM 204800
#define M_DIM 32
#define N_DIM 256
#define SPLIT 296              // = 2 * 148 SMs
#define TILES_TOTAL 6400       // K / 32

__device__ float g_partial[SPLIT * M_DIM * N_DIM];   // 9.7 MB
__device__ float g_h0[M_DIM * N_DIM];
__device__ float g_h1[M_DIM * N_DIM];

typedef unsigned long long u64;

__device__ __forceinline__ float elu(float v) { return v > 0.0f ? v : expm1f(v); }

__device__ __forceinline__ u64 pack2(float lo, float hi) {
    u64 r; asm("mov.b64 %0, {%1, %2};" : "=l"(r) : "f"(lo), "f"(hi)); return r;
}
__device__ __forceinline__ void unpack2(u64 v, float& lo, float& hi) {
    asm("mov.b64 {%0, %1}, %2;" : "=f"(lo), "=f"(hi) : "l"(v));
}
__device__ __forceinline__ void ffma2(u64& d, u64 a, u64 b) {
    asm("fma.rn.f32x2 %0, %1, %2, %0;" : "+l"(d) : "l"(a), "l"(b));
}
__device__ __forceinline__ uint32_t smem_u32(const void* p) {
    uint32_t a;
    asm("{ .reg .u64 t; cvta.to.shared.u64 t, %1; cvt.u32.u64 %0, t; }" : "=r"(a) : "l"(p));
    return a;
}
__device__ __forceinline__ uint32_t packh2(float a, float b) {
    __half2 h = __floats2half2_rn(a, b);
    return *reinterpret_cast<uint32_t*>(&h);
}
__device__ __forceinline__ void mma_f16(float* d, const uint32_t* a,
                                        uint32_t b0, uint32_t b1) {
    asm volatile(
        "mma.sync.aligned.m16n8k16.row.col.f32.f16.f16.f32 "
        "{%0,%1,%2,%3}, {%4,%5,%6,%7}, {%8,%9}, {%0,%1,%2,%3};"
        : "+f"(d[0]), "+f"(d[1]), "+f"(d[2]), "+f"(d[3])
        : "r"(a[0]), "r"(a[1]), "r"(a[2]), "r"(a[3]), "r"(b0), "r"(b1));
}

// smem layout (fp32 words)
#define BPADW 260
#define BSTW  (32 * BPADW)             // 8320 words per B stage
#define NSTG  3
#define AOFFW (NSTG * BSTW)            // 24960
#define AMP   36                       // A pair-row m-stride (uint2 units)
#define APLW  (8 * AMP * 2)            // words per A plane = 576
#define SMEM_WORDS (AOFFW + 2 * APLW)  // 26112 words = 104448 B

// ---------------------------------------------------------------------------
// K1: cp.async 3-stage pipeline; fp16 1-term compute.
// ---------------------------------------------------------------------------
__global__ __launch_bounds__(256, 2)
void gemm0_mma(const float* __restrict__ x, const float* __restrict__ W0) {
    extern __shared__ uint32_t sm[];
    const uint32_t sb = smem_u32(sm);

    const int tid  = threadIdx.x;
    const int w    = tid >> 5;
    const int lane = tid & 31;
    const int g    = lane >> 2;    // 0..7
    const int tg   = lane & 3;     // 0..3
    const int nbase = w * 32;

    const int tl_beg = (int)(((long)blockIdx.x       * TILES_TOTAL) / SPLIT);
    const int tl_end = (int)(((long)(blockIdx.x + 1) * TILES_TOTAL) / SPLIT);
    const int T = tl_end - tl_beg;   // 21 or 22

    const int am[2]  = { (0*256+tid) >> 4, (1*256+tid) >> 4 };
    const int akp[2] = { (0*256+tid) & 15, (1*256+tid) & 15 };

    float d[2][4][4];
#pragma unroll
    for (int mt = 0; mt < 2; mt++)
#pragma unroll
        for (int j = 0; j < 4; j++)
#pragma unroll
            for (int r = 0; r < 4; r++) d[mt][j][r] = 0.0f;

    auto issueB = [&](int tl, int slot) {
        const float* gsrc = W0 + (long)tl * 32 * N_DIM;
        const uint32_t sdst = sb + (uint32_t)(slot * BSTW) * 4u;
#pragma unroll
        for (int it = 0; it < 8; it++) {
            const int id  = it * 256 + tid;
            const int row = id >> 6;
            const int col = (id & 63) * 4;
            const uint32_t dst = sdst + (uint32_t)(row * BPADW + col) * 4u;
            const float* src = gsrc + row * N_DIM + col;
            asm volatile("cp.async.cg.shared.global [%0], [%1], 16;"
                         :: "r"(dst), "l"(src));
        }
    };

    float2 ar[2];
    auto ldgA = [&](int tl) {
#pragma unroll
        for (int it = 0; it < 2; it++)
            ar[it] = *(const float2*)(x + (long)am[it] * K_DIM + tl * 32 + 2 * akp[it]);
    };
    // A layout: plane[q][m] uint2 = {kp = s*8+tq, kp+4}, q = s*4+tq
    auto stsA = [&](int slot) {
        uint32_t* Ah = sm + AOFFW + slot * APLW;
#pragma unroll
        for (int it = 0; it < 2; it++) {
            const uint32_t h = packh2(ar[it].x, ar[it].y);
            const int kp = akp[it];
            const int s_ = kp >> 3;
            const int tq = kp & 3;
            const int hf = (kp >> 2) & 1;
            Ah[((s_ * 4 + tq) * AMP + am[it]) * 2 + hf] = h;
        }
    };

    // prologue
    issueB(tl_beg, 0);
    asm volatile("cp.async.commit_group;");
    issueB(tl_beg + 1, 1);
    asm volatile("cp.async.commit_group;");
    ldgA(tl_beg);
    stsA(0);
    ldgA(tl_beg + 1);

    for (int i = 0; i < T; i++) {
        asm volatile("cp.async.wait_group 1;");
        __syncthreads();

        if (i + 2 < T) issueB(tl_beg + i + 2, (i + 2) % NSTG);
        asm volatile("cp.async.commit_group;");
        if (i + 1 < T) stsA((i + 1) & 1);
        if (i + 2 < T) ldgA(tl_beg + i + 2);

        const float*    Bb = (const float*)(sm) + (i % NSTG) * BSTW;
        const uint32_t* Ah = sm + AOFFW + (i & 1) * APLW;

#pragma unroll
        for (int s = 0; s < 2; s++) {
            const int q   = s * 4 + tg;
            const int kp0 = s * 8 + tg;

            uint32_t ah[2][4];
#pragma unroll
            for (int mt = 0; mt < 2; mt++) {
                const int m0 = mt * 16 + g;
                const uint2 pa0 = *(const uint2*)(Ah + (q * AMP + m0) * 2);
                const uint2 pa1 = *(const uint2*)(Ah + (q * AMP + m0 + 8) * 2);
                ah[mt][0] = pa0.x; ah[mt][2] = pa0.y;
                ah[mt][1] = pa1.x; ah[mt][3] = pa1.y;
            }

            const int kr0 = 2 * kp0;
            const int kr1 = kr0 + 8;
            const float4 r0 = *(const float4*)(Bb + kr0 * BPADW + nbase + 4 * g);
            const float4 r1 = *(const float4*)(Bb + (kr0 + 1) * BPADW + nbase + 4 * g);
            const float4 r2 = *(const float4*)(Bb + kr1 * BPADW + nbase + 4 * g);
            const float4 r3 = *(const float4*)(Bb + (kr1 + 1) * BPADW + nbase + 4 * g);
            uint32_t bh[4][2];
            bh[0][0] = packh2(r0.x, r1.x); bh[0][1] = packh2(r2.x, r3.x);
            bh[1][0] = packh2(r0.y, r1.y); bh[1][1] = packh2(r2.y, r3.y);
            bh[2][0] = packh2(r0.z, r1.z); bh[2][1] = packh2(r2.z, r3.z);
            bh[3][0] = packh2(r0.w, r1.w); bh[3][1] = packh2(r2.w, r3.w);

#pragma unroll
            for (int j = 0; j < 4; j++)
#pragma unroll
                for (int mt = 0; mt < 2; mt++)
                    mma_f16(d[mt][j], ah[mt], bh[j][0], bh[j][1]);
        }
    }

    // epilogue: tile j col (2tg+delta) -> logical n = nbase + 4*(2tg+delta)+j
    float* po = g_partial + blockIdx.x * (M_DIM * N_DIM);
#pragma unroll
    for (int mt = 0; mt < 2; mt++) {
#pragma unroll
        for (int j = 0; j < 4; j++) {
            const int m0 = mt * 16 + g;
            const int c0 = nbase + 8 * tg + j;
            po[m0 * N_DIM + c0]           = d[mt][j][0];
            po[m0 * N_DIM + c0 + 4]       = d[mt][j][1];
            po[(m0 + 8) * N_DIM + c0]     = d[mt][j][2];
            po[(m0 + 8) * N_DIM + c0 + 4] = d[mt][j][3];
        }
    }
}

// ---------------------------------------------------------------------------
// K2: reduce 296 partials (fixed order -> deterministic) + b0 + ELU.
// ---------------------------------------------------------------------------
__global__ __launch_bounds__(256)
void reduce_kernel(const float* __restrict__ b0) {
    __shared__ float red[8][32];
    const int m  = blockIdx.x >> 3;
    const int nc = (blockIdx.x & 7) * 32;
    const int nl = threadIdx.x & 31;
    const int sl = threadIdx.x >> 5;
    const int n  = nc + nl;

    float s = 0.0f;
    const float* p = g_partial + (sl * 37) * (M_DIM * N_DIM) + m * N_DIM + n;
#pragma unroll
    for (int i = 0; i < 37; i++) s += p[i * (M_DIM * N_DIM)];
    red[sl][nl] = s;
    __syncthreads();
    if (sl == 0) {
        float a = b0[n];
#pragma unroll
        for (int j = 0; j < 8; j++) a += red[j][nl];
        g_h0[m * N_DIM + n] = elu(a);
    }
}

// ---------------------------------------------------------------------------
// K3: h1 = ELU(h0 @ W1 + b1). 256 blocks: (m, 32-wide n chunk).
// ---------------------------------------------------------------------------
__global__ __launch_bounds__(256)
void mlp1_kernel(const float* __restrict__ W1, const float* __restrict__ b1) {
    __shared__ float red[8][32];
    const int m  = blockIdx.x >> 3;
    const int nc = (blockIdx.x & 7) * 32;
    const int nl = threadIdx.x & 31;
    const int sl = threadIdx.x >> 5;
    const int n  = nc + nl;

    float s = 0.0f;
    const float* hr = g_h0 + m * N_DIM;
#pragma unroll
    for (int k = 0; k < 32; k++)
        s += hr[sl * 32 + k] * W1[(sl * 32 + k) * 256 + n];
    red[sl][nl] = s;
    __syncthreads();
    if (sl == 0) {
        float a = b1[n];
#pragma unroll
        for (int j = 0; j < 8; j++) a += red[j][nl];
        g_h1[m * N_DIM + n] = elu(a);
    }
}

// ---------------------------------------------------------------------------
// K4: gconv with fused logits+softmax prologue. 128 thr = 4 warps.
// Prologue: warp e computes logit e (k-split + shfl), softmax -> wsm[4].
// Then expert mix, staged x, 2 channels/thread compute, staged output.
// ---------------------------------------------------------------------------
__global__ __launch_bounds__(128)
void gconv_kernel(const float* __restrict__ x, const float* __restrict__ A,
                  const float* __restrict__ W2, const float* __restrict__ b2,
                  float* __restrict__ out) {
    __shared__ __align__(16) float ASs[4][650];   // 10.4 KB
    __shared__ float buf[64 * 101];               // 25.9 KB (xs then os)
    __shared__ float lgs[4];
    __shared__ float wsm[4];
    const int tid = threadIdx.x;
    const int n   = blockIdx.y;
    const int t0  = blockIdx.x * 4;

    // ---- fused softmax ----
    {
        const int e    = tid >> 5;
        const int lane = tid & 31;
        float s = 0.0f;
        const float* hr = g_h1 + n * N_DIM;
#pragma unroll
        for (int k = lane; k < 256; k += 32) s += hr[k] * W2[k * 4 + e];
#pragma unroll
        for (int o = 16; o; o >>= 1) s += __shfl_xor_sync(0xffffffffu, s, o);
        if (lane == 0) lgs[e] = s + b2[e];
    }
    __syncthreads();
    if (tid < 4) {
        const float l0 = lgs[0], l1 = lgs[1], l2 = lgs[2], l3 = lgs[3];
        const float mx = fmaxf(fmaxf(l0, l1), fmaxf(l2, l3));
        const float e0 = expf(l0 - mx), e1 = expf(l1 - mx);
        const float e2 = expf(l2 - mx), e3 = expf(l3 - mx);
        const float inv = 1.0f / (e0 + e1 + e2 + e3);
        const float ev = (tid == 0) ? e0 : (tid == 1) ? e1 : (tid == 2) ? e2 : e3;
        wsm[tid] = ev * inv;
    }
    __syncthreads();

    const float w0 = wsm[0], w1 = wsm[1], w2 = wsm[2], w3 = wsm[3];

    for (int idx = tid; idx < 2500; idx += 128) {
        const int grp = idx / 625;
        const int j   = idx - grp * 625;
        const int v   = j / 25;
        const int ww  = j - v * 25;
        const float* At = A + (t0 + grp) * 625 + j;
        ASs[grp][v * 26 + ww] = w0 * At[0]
                              + w1 * At[1 * 128 * 625]
                              + w2 * At[2 * 128 * 625]
                              + w3 * At[3 * 128 * 625];
    }

    const float* xb = x + n * K_DIM + t0 * 25;
#pragma unroll 10
    for (int u = 0; u < 50; u++) {
        const int idx = u * 128 + tid;
        const int c = idx / 100;
        const int j = idx - c * 100;
        const int grp = j / 25;
        const int v   = j - grp * 25;
        buf[grp * 1600 + c * 25 + v] = xb[c * 3200 + j];
    }
    __syncthreads();

    const int grp = tid >> 5;
    const int c0  = tid & 31;
    const float* xg = &buf[grp * 1600];
    const float* Ab = &ASs[grp][0];

    u64 accA[12], accB[12];
#pragma unroll
    for (int p = 0; p < 12; p++) { accA[p] = 0ull; accB[p] = 0ull; }
    float a24 = 0.0f, b24 = 0.0f;

#pragma unroll
    for (int v = 0; v < 25; v++) {
        const float x0 = xg[c0 * 25 + v];
        const float x1 = xg[(c0 + 32) * 25 + v];
        const u64 g0 = pack2(x0, x0);
        const u64 g1 = pack2(x1, x1);
        const float* row = Ab + v * 26;
#pragma unroll
        for (int p = 0; p < 12; p++) {
            const u64 wv = *(const u64*)(row + 2 * p);
            ffma2(accA[p], g0, wv);
            ffma2(accB[p], g1, wv);
        }
        const float aw = row[24];
        a24 += x0 * aw;
        b24 += x1 * aw;
    }

    __syncthreads();

    {
        float* osA = &buf[c0 * 101 + grp * 25];
        float* osB = &buf[(c0 + 32) * 101 + grp * 25];
#pragma unroll
        for (int p = 0; p < 12; p++) {
            float lo, hi;
            unpack2(accA[p], lo, hi);
            osA[2 * p] = lo; osA[2 * p + 1] = hi;
            unpack2(accB[p], lo, hi);
            osB[2 * p] = lo; osB[2 * p + 1] = hi;
        }
        osA[24] = a24;
        osB[24] = b24;
    }
    __syncthreads();

    float* ob = out + n * K_DIM + t0 * 25;
#pragma unroll 10
    for (int u = 0; u < 50; u++) {
        const int idx = u * 128 + tid;
        const int c2 = idx / 100;
        const int j  = idx - c2 * 100;
        ob[c2 * 3200 + j] = buf[c2 * 101 + j];
    }
}

// ---------------------------------------------------------------------------
extern "C" void kernel_launch(void* const* d_in, const int* in_sizes, int n_in,
                              void* d_out, int out_size) {
    const float* x  = (const float*)d_in[0];
    const float* W0 = (const float*)d_in[1];
    const float* b0 = (const float*)d_in[2];
    const float* W1 = (const float*)d_in[3];
    const float* b1 = (const float*)d_in[4];
    const float* W2 = (const float*)d_in[5];
    const float* b2 = (const float*)d_in[6];
    const float* A  = (const float*)d_in[7];
    float* out = (float*)d_out;

    cudaFuncSetAttribute(gemm0_mma, cudaFuncAttributeMaxDynamicSharedMemorySize,
                         SMEM_WORDS * 4);

    gemm0_mma<<<SPLIT, 256, SMEM_WORDS * 4>>>(x, W0);
    reduce_kernel<<<256, 256>>>(b0);
    mlp1_kernel<<<256, 256>>>(W1, b1);
    gconv_kernel<<<dim3(32, 32), 128>>>(x, A, W2, b2, out);
}